// round 10
// baseline (speedup 1.0000x reference)
#include <cuda_runtime.h>

#define N_NODES 100000
#define N_EDGES 1600000
#define DIN 8
#define H 32
#define WPAD 36            // padded transposed-weight row stride (floats)
#define FULL 0xffffffffu

#define SCAN_ELEMS 2048
#define NUM_SCAN_BLOCKS ((N_NODES + SCAN_ELEMS - 1) / SCAN_ELEMS)   // 49
#define L1_BLOCKS  888     // layer1: 6 blocks/SM (measured best)
#define L23_BLOCKS 592     // layers 2/3: 4 blocks/SM (measured best)

// ---------------- scratch (device globals; no allocation allowed) ----------
__device__ int   g_counts[N_NODES];
__device__ int   g_offsets[N_NODES + 1];
__device__ int   g_rank[N_EDGES];
__device__ int   g_csr[N_EDGES];
__device__ float g_hA[N_NODES * H];
__device__ float g_hB[N_NODES * H];
__device__ int   g_blockAgg[NUM_SCAN_BLOCKS];
__device__ int   g_blockPrefix[NUM_SCAN_BLOCKS];
__device__ int   g_blockFlag[NUM_SCAN_BLOCKS];   // 0=none 1=agg 2=prefix
__device__ int   g_scanCounter;

// ---------------- hist (counts pre-zeroed by previous replay's k_fill) ------
__global__ void k_hist(const int* __restrict__ dst) {
    int i = blockIdx.x * blockDim.x + threadIdx.x;
    if (i < N_EDGES / 4) {
        int4 d = ((const int4*)dst)[i];
        int4 r;
        r.x = atomicAdd(&g_counts[d.x], 1);
        r.y = atomicAdd(&g_counts[d.y], 1);
        r.z = atomicAdd(&g_counts[d.z], 1);
        r.w = atomicAdd(&g_counts[d.w], 1);
        ((int4*)g_rank)[i] = r;
    }
}

// ---------------- single-pass decoupled-lookback exclusive scan --------------
__global__ void __launch_bounds__(512) k_scan() {
    __shared__ int s_warpSums[16];
    __shared__ int s_bid;
    __shared__ int s_exclBase;

    int t = threadIdx.x;
    if (t == 0) s_bid = atomicAdd(&g_scanCounter, 1);
    __syncthreads();
    int bid  = s_bid;
    int base = bid * SCAN_ELEMS;
    int idx  = base + t * 4;
    int lane = t & 31, wid = t >> 5;

    int4 v;
    if (idx + 3 < N_NODES) {
        v = ((const int4*)g_counts)[idx >> 2];
    } else {
        v.x = (idx + 0 < N_NODES) ? g_counts[idx + 0] : 0;
        v.y = (idx + 1 < N_NODES) ? g_counts[idx + 1] : 0;
        v.z = (idx + 2 < N_NODES) ? g_counts[idx + 2] : 0;
        v.w = (idx + 3 < N_NODES) ? g_counts[idx + 3] : 0;
    }
    int tsum = v.x + v.y + v.z + v.w;
    int tIncl = tsum;
#pragma unroll
    for (int off = 1; off < 32; off <<= 1) {
        int u = __shfl_up_sync(FULL, tIncl, off);
        if (lane >= off) tIncl += u;
    }
    if (lane == 31) s_warpSums[wid] = tIncl;
    __syncthreads();

    if (t == 0) {
        int run = 0;
#pragma unroll
        for (int i = 0; i < 16; i++) { int a = s_warpSums[i]; s_warpSums[i] = run; run += a; }
        if (bid == 0) {
            g_blockPrefix[0] = run;
            __threadfence();
            ((volatile int*)g_blockFlag)[0] = 2;
            s_exclBase = 0;
        } else {
            g_blockAgg[bid] = run;
            __threadfence();
            ((volatile int*)g_blockFlag)[bid] = 1;
            int running = 0;
            int j = bid - 1;
            while (true) {
                int f;
                while ((f = ((volatile int*)g_blockFlag)[j]) == 0) { }
                __threadfence();
                if (f == 2) { running += ((volatile int*)g_blockPrefix)[j]; break; }
                running += ((volatile int*)g_blockAgg)[j];
                j--;
            }
            g_blockPrefix[bid] = running + run;
            __threadfence();
            ((volatile int*)g_blockFlag)[bid] = 2;
            s_exclBase = running;
        }
    }
    __syncthreads();

    int e0 = s_exclBase + s_warpSums[wid] + (tIncl - tsum);
    int4 o;
    o.x = e0;
    o.y = e0 + v.x;
    o.z = o.y + v.y;
    o.w = o.z + v.z;
    if (idx + 3 < N_NODES) {
        ((int4*)g_offsets)[idx >> 2] = o;
    } else {
        if (idx + 0 < N_NODES) g_offsets[idx + 0] = o.x;
        if (idx + 1 < N_NODES) g_offsets[idx + 1] = o.y;
        if (idx + 2 < N_NODES) g_offsets[idx + 2] = o.z;
        if (idx + 3 < N_NODES) g_offsets[idx + 3] = o.w;
    }
}

// ---------------- fill (atomic-free) + re-zero state for next replay ---------
__global__ void k_fill(const int* __restrict__ src,
                       const int* __restrict__ dst) {
    int i = blockIdx.x * blockDim.x + threadIdx.x;
    if (i < N_EDGES / 4) {
        int4 d = ((const int4*)dst)[i];
        int4 s = ((const int4*)src)[i];
        int4 r = ((const int4*)g_rank)[i];
        g_csr[g_offsets[d.x] + r.x] = s.x;
        g_csr[g_offsets[d.y] + r.y] = s.y;
        g_csr[g_offsets[d.z] + r.z] = s.z;
        g_csr[g_offsets[d.w] + r.w] = s.w;
    }
    // counts are dead after k_scan; zero them for the NEXT graph replay
    if (i < N_NODES / 4) ((int4*)g_counts)[i] = make_int4(0, 0, 0, 0);
    if (i < NUM_SCAN_BLOCKS) g_blockFlag[i] = 0;
    if (i == 0) {
        g_scanCounter = 0;
        g_offsets[N_NODES] = N_EDGES;   // sentinel for cnt computation this replay
    }
}

// ---------------- layer 1: x[N,8] -> g_hA[N,32]  (888 persistent blocks) ----
__global__ void __launch_bounds__(256, 6) k_layer1(const float* __restrict__ x,
                                                   const float* __restrict__ Wl,
                                                   const float* __restrict__ bl,
                                                   const float* __restrict__ Wr) {
    __shared__ float Wls[DIN * H], Wrs[DIN * H], bls[H];
    __shared__ float4 msm4[8][2];
    __shared__ float  xsm[8][8];
    for (int i = threadIdx.x; i < DIN * H; i += blockDim.x) {
        Wls[i] = Wl[i];
        Wrs[i] = Wr[i];
    }
    if (threadIdx.x < H) bls[threadIdx.x] = bl[threadIdx.x];
    __syncthreads();

    int lane  = threadIdx.x & 31;
    int w     = threadIdx.x >> 5;
    int gwarp = blockIdx.x * 8 + w;
    int sub = lane >> 1, q = lane & 1;
    const float4* x4 = (const float4*)x;

    for (int n = gwarp; n < N_NODES; n += L1_BLOCKS * 8) {
        int base = g_offsets[n];
        int cnt  = g_offsets[n + 1] - base;

        float4 acc = make_float4(0.f, 0.f, 0.f, 0.f);
        int s0 = (sub < cnt) ? g_csr[base + sub] : -1;
        for (int i = 0; i < cnt; i += 16) {
            int en = i + 16 + sub;
            int sn = (en < cnt) ? g_csr[base + en] : -1;
            if (s0 >= 0) {
                float4 v = __ldcg(&x4[s0 * 2 + q]);      // L2-only: no L1 reuse
                acc.x += v.x; acc.y += v.y; acc.z += v.z; acc.w += v.w;
            }
            s0 = sn;
        }
#pragma unroll
        for (int off = 16; off >= 2; off >>= 1) {
            acc.x += __shfl_down_sync(FULL, acc.x, off);
            acc.y += __shfl_down_sync(FULL, acc.y, off);
            acc.z += __shfl_down_sync(FULL, acc.z, off);
            acc.w += __shfl_down_sync(FULL, acc.w, off);
        }
        float inv = 1.f / fmaxf((float)cnt, 1.f);
        if (lane < 2) {
            msm4[w][lane] = make_float4(acc.x * inv, acc.y * inv, acc.z * inv, acc.w * inv);
        }
        if (lane < 8) xsm[w][lane] = __ldcg(&x[n * DIN + lane]);
        __syncwarp();

        const float* ms = (const float*)msm4[w];
        float o = bls[lane];
#pragma unroll
        for (int k = 0; k < DIN; k++) {
            o += ms[k] * Wls[k * H + lane] + xsm[w][k] * Wrs[k * H + lane];
        }
        __stcg(&g_hA[n * H + lane], fmaxf(o, 0.f));      // no L1 allocation
        __syncwarp();
    }
}

// ---------------- generic SAGE layer (32->32) gather+matmul (lean) ----------
__device__ __forceinline__ float sage32(const float* __restrict__ hin,
                                        int n, int lane, int w,
                                        const float* __restrict__ wlT,
                                        const float* __restrict__ wrT,
                                        const float* __restrict__ bls,
                                        float4 (*ms4)[8], float4 (*hs4)[8]) {
    int base = g_offsets[n];
    int cnt  = g_offsets[n + 1] - base;
    int sub = lane >> 3, q = lane & 7;
    const float4* h4 = (const float4*)hin;

    float4 acc = make_float4(0.f, 0.f, 0.f, 0.f);
    int s0 = (sub < cnt) ? g_csr[base + sub] : -1;
    for (int i = 0; i < cnt; i += 4) {
        int en = i + 4 + sub;
        int sn = (en < cnt) ? g_csr[base + en] : -1;
        if (s0 >= 0) {
            float4 v = __ldcg(&h4[s0 * 8 + q]);          // L2-only: no L1 reuse
            acc.x += v.x; acc.y += v.y; acc.z += v.z; acc.w += v.w;
        }
        s0 = sn;
    }
#pragma unroll
    for (int off = 16; off >= 8; off >>= 1) {
        acc.x += __shfl_down_sync(FULL, acc.x, off);
        acc.y += __shfl_down_sync(FULL, acc.y, off);
        acc.z += __shfl_down_sync(FULL, acc.z, off);
        acc.w += __shfl_down_sync(FULL, acc.w, off);
    }
    float inv = 1.f / fmaxf((float)cnt, 1.f);
    if (lane < 8) {
        ms4[w][lane] = make_float4(acc.x * inv, acc.y * inv, acc.z * inv, acc.w * inv);
    }
    float hv = __ldcg(&hin[n * H + lane]);
    ((float*)hs4[w])[lane] = hv;
    __syncwarp();

    const float4* wl4 = (const float4*)(wlT + lane * WPAD);
    const float4* wr4 = (const float4*)(wrT + lane * WPAD);
    float o = bls[lane];
#pragma unroll
    for (int kk = 0; kk < 8; kk++) {
        float4 m4 = ms4[w][kk];
        float4 v4 = hs4[w][kk];
        float4 a4 = wl4[kk];
        float4 b4 = wr4[kk];
        o += m4.x * a4.x + m4.y * a4.y + m4.z * a4.z + m4.w * a4.w;
        o += v4.x * b4.x + v4.y * b4.y + v4.z * b4.z + v4.w * b4.w;
    }
    return o;
}

// ---------------- layer 2: g_hA -> g_hB  (592 persistent blocks) -------------
__global__ void __launch_bounds__(256) k_layer2(const float* __restrict__ Wl,
                                                const float* __restrict__ bl,
                                                const float* __restrict__ Wr) {
    __shared__ float wlT[H * WPAD], wrT[H * WPAD], bls[H];
    __shared__ float4 ms4[8][8], hs4[8][8];
    for (int i = threadIdx.x; i < H * H; i += blockDim.x) {
        int k = i >> 5, c = i & 31;
        wlT[c * WPAD + k] = Wl[i];
        wrT[c * WPAD + k] = Wr[i];
    }
    if (threadIdx.x < H) bls[threadIdx.x] = bl[threadIdx.x];
    __syncthreads();

    int lane  = threadIdx.x & 31;
    int w     = threadIdx.x >> 5;
    int gwarp = blockIdx.x * 8 + w;

    for (int n = gwarp; n < N_NODES; n += L23_BLOCKS * 8) {
        float o = sage32(g_hA, n, lane, w, wlT, wrT, bls, ms4, hs4);
        __stcg(&g_hB[n * H + lane], fmaxf(o, 0.f));
        __syncwarp();
    }
}

// ---------------- layer 3 + MLP head: g_hB -> out[N,3] (592 persistent) -----
__global__ void __launch_bounds__(256) k_layer3_head(float* __restrict__ out,
                                                     const float* __restrict__ Wl,
                                                     const float* __restrict__ bl,
                                                     const float* __restrict__ Wr,
                                                     const float* __restrict__ Wh1,
                                                     const float* __restrict__ bh1,
                                                     const float* __restrict__ Wh2,
                                                     const float* __restrict__ bh2) {
    __shared__ float wlT[H * WPAD], wrT[H * WPAD], w1T[H * WPAD];
    __shared__ float bls[H], b1s[H], W2s[H * 3], b2s[3];
    __shared__ float4 ms4[8][8], hs4[8][8];
    for (int i = threadIdx.x; i < H * H; i += blockDim.x) {
        int k = i >> 5, c = i & 31;
        wlT[c * WPAD + k] = Wl[i];
        wrT[c * WPAD + k] = Wr[i];
        w1T[c * WPAD + k] = Wh1[i];
    }
    if (threadIdx.x < H) {
        bls[threadIdx.x] = bl[threadIdx.x];
        b1s[threadIdx.x] = bh1[threadIdx.x];
    }
    for (int i = threadIdx.x; i < H * 3; i += blockDim.x) W2s[i] = Wh2[i];
    if (threadIdx.x < 3) b2s[threadIdx.x] = bh2[threadIdx.x];
    __syncthreads();

    int lane  = threadIdx.x & 31;
    int w     = threadIdx.x >> 5;
    int gwarp = blockIdx.x * 8 + w;

    for (int n = gwarp; n < N_NODES; n += L23_BLOCKS * 8) {
        float o = sage32(g_hB, n, lane, w, wlT, wrT, bls, ms4, hs4);
        float h3 = fmaxf(o, 0.f);

        // head layer 1: 32 -> 32, relu
        __syncwarp();
        ((float*)hs4[w])[lane] = h3;
        __syncwarp();
        const float4* w14 = (const float4*)(w1T + lane * WPAD);
        float t1 = b1s[lane];
#pragma unroll
        for (int kk = 0; kk < 8; kk++) {
            float4 v4 = hs4[w][kk];
            float4 a4 = w14[kk];
            t1 += v4.x * a4.x + v4.y * a4.y + v4.z * a4.z + v4.w * a4.w;
        }
        t1 = fmaxf(t1, 0.f);

        // head layer 2: 32 -> 3, warp reduction
        float p0 = t1 * W2s[lane * 3 + 0];
        float p1 = t1 * W2s[lane * 3 + 1];
        float p2 = t1 * W2s[lane * 3 + 2];
#pragma unroll
        for (int off = 16; off > 0; off >>= 1) {
            p0 += __shfl_xor_sync(FULL, p0, off);
            p1 += __shfl_xor_sync(FULL, p1, off);
            p2 += __shfl_xor_sync(FULL, p2, off);
        }
        if (lane == 0) {
            out[n * 3 + 0] = p0 + b2s[0];
            out[n * 3 + 1] = p1 + b2s[1];
            out[n * 3 + 2] = p2 + b2s[2];
        }
        __syncwarp();
    }
}

// ---------------- launcher ---------------------------------------------------
extern "C" void kernel_launch(void* const* d_in, const int* in_sizes, int n_in,
                              void* d_out, int out_size) {
    const float* x   = (const float*)d_in[0];
    const int*   ei  = (const int*)d_in[1];    // int64 in reference -> int32 on device
    const int*   src = ei;
    const int*   dst = ei + N_EDGES;
    const float* Wl1 = (const float*)d_in[2];
    const float* bl1 = (const float*)d_in[3];
    const float* Wr1 = (const float*)d_in[4];
    const float* Wl2 = (const float*)d_in[5];
    const float* bl2 = (const float*)d_in[6];
    const float* Wr2 = (const float*)d_in[7];
    const float* Wl3 = (const float*)d_in[8];
    const float* bl3 = (const float*)d_in[9];
    const float* Wr3 = (const float*)d_in[10];
    const float* Wh1 = (const float*)d_in[11];
    const float* bh1 = (const float*)d_in[12];
    const float* Wh2 = (const float*)d_in[13];
    const float* bh2 = (const float*)d_in[14];
    float* out = (float*)d_out;

    k_hist<<<(N_EDGES / 4 + 255) / 256, 256>>>(dst);
    k_scan<<<NUM_SCAN_BLOCKS, 512>>>();
    k_fill<<<(N_EDGES / 4 + 255) / 256, 256>>>(src, dst);

    k_layer1<<<L1_BLOCKS, 256>>>(x, Wl1, bl1, Wr1);
    k_layer2<<<L23_BLOCKS, 256>>>(Wl2, bl2, Wr2);
    k_layer3_head<<<L23_BLOCKS, 256>>>(out, Wl3, bl3, Wr3, Wh1, bh1, Wh2, bh2);
}

// round 11
// speedup vs baseline: 1.1235x; 1.1235x over previous
#include <cuda_runtime.h>

#define N_NODES 100000
#define N_PAIRS (N_NODES / 2)
#define N_EDGES 1600000
#define DIN 8
#define H 32
#define WPAD 36            // padded transposed-weight row stride (floats)
#define FULL 0xffffffffu

#define SCAN_ELEMS 2048
#define NUM_SCAN_BLOCKS ((N_NODES + SCAN_ELEMS - 1) / SCAN_ELEMS)   // 49
#define L1_BLOCKS  888     // layer1: 6 blocks/SM (measured best)
#define L23_BLOCKS 592     // layers 2/3: 4 blocks/SM (measured best)

// ---------------- scratch (device globals; no allocation allowed) ----------
__device__ int   g_counts[N_NODES];
__device__ int   g_offsets[N_NODES + 1];
__device__ int   g_rank[N_EDGES];
__device__ int   g_csr[N_EDGES];
__device__ float g_hA[N_NODES * H];
__device__ float g_hB[N_NODES * H];
__device__ int   g_blockAgg[NUM_SCAN_BLOCKS];
__device__ int   g_blockPrefix[NUM_SCAN_BLOCKS];
__device__ int   g_blockFlag[NUM_SCAN_BLOCKS];   // 0=none 1=agg 2=prefix
__device__ int   g_scanCounter;

// ---------------- hist (counts pre-zeroed by previous replay's k_fill) ------
__global__ void k_hist(const int* __restrict__ dst) {
    int i = blockIdx.x * blockDim.x + threadIdx.x;
    if (i < N_EDGES / 4) {
        int4 d = ((const int4*)dst)[i];
        int4 r;
        r.x = atomicAdd(&g_counts[d.x], 1);
        r.y = atomicAdd(&g_counts[d.y], 1);
        r.z = atomicAdd(&g_counts[d.z], 1);
        r.w = atomicAdd(&g_counts[d.w], 1);
        ((int4*)g_rank)[i] = r;
    }
}

// ---------------- single-pass decoupled-lookback exclusive scan --------------
__global__ void __launch_bounds__(512) k_scan() {
    __shared__ int s_warpSums[16];
    __shared__ int s_bid;
    __shared__ int s_exclBase;

    int t = threadIdx.x;
    if (t == 0) s_bid = atomicAdd(&g_scanCounter, 1);
    __syncthreads();
    int bid  = s_bid;
    int base = bid * SCAN_ELEMS;
    int idx  = base + t * 4;
    int lane = t & 31, wid = t >> 5;

    int4 v;
    if (idx + 3 < N_NODES) {
        v = ((const int4*)g_counts)[idx >> 2];
    } else {
        v.x = (idx + 0 < N_NODES) ? g_counts[idx + 0] : 0;
        v.y = (idx + 1 < N_NODES) ? g_counts[idx + 1] : 0;
        v.z = (idx + 2 < N_NODES) ? g_counts[idx + 2] : 0;
        v.w = (idx + 3 < N_NODES) ? g_counts[idx + 3] : 0;
    }
    int tsum = v.x + v.y + v.z + v.w;
    int tIncl = tsum;
#pragma unroll
    for (int off = 1; off < 32; off <<= 1) {
        int u = __shfl_up_sync(FULL, tIncl, off);
        if (lane >= off) tIncl += u;
    }
    if (lane == 31) s_warpSums[wid] = tIncl;
    __syncthreads();

    if (t == 0) {
        int run = 0;
#pragma unroll
        for (int i = 0; i < 16; i++) { int a = s_warpSums[i]; s_warpSums[i] = run; run += a; }
        if (bid == 0) {
            g_blockPrefix[0] = run;
            __threadfence();
            ((volatile int*)g_blockFlag)[0] = 2;
            s_exclBase = 0;
        } else {
            g_blockAgg[bid] = run;
            __threadfence();
            ((volatile int*)g_blockFlag)[bid] = 1;
            int running = 0;
            int j = bid - 1;
            while (true) {
                int f;
                while ((f = ((volatile int*)g_blockFlag)[j]) == 0) { }
                __threadfence();
                if (f == 2) { running += ((volatile int*)g_blockPrefix)[j]; break; }
                running += ((volatile int*)g_blockAgg)[j];
                j--;
            }
            g_blockPrefix[bid] = running + run;
            __threadfence();
            ((volatile int*)g_blockFlag)[bid] = 2;
            s_exclBase = running;
        }
    }
    __syncthreads();

    int e0 = s_exclBase + s_warpSums[wid] + (tIncl - tsum);
    int4 o;
    o.x = e0;
    o.y = e0 + v.x;
    o.z = o.y + v.y;
    o.w = o.z + v.z;
    if (idx + 3 < N_NODES) {
        ((int4*)g_offsets)[idx >> 2] = o;
    } else {
        if (idx + 0 < N_NODES) g_offsets[idx + 0] = o.x;
        if (idx + 1 < N_NODES) g_offsets[idx + 1] = o.y;
        if (idx + 2 < N_NODES) g_offsets[idx + 2] = o.z;
        if (idx + 3 < N_NODES) g_offsets[idx + 3] = o.w;
    }
}

// ---------------- fill (atomic-free) + re-zero state for next replay ---------
__global__ void k_fill(const int* __restrict__ src,
                       const int* __restrict__ dst) {
    int i = blockIdx.x * blockDim.x + threadIdx.x;
    if (i < N_EDGES / 4) {
        int4 d = ((const int4*)dst)[i];
        int4 s = ((const int4*)src)[i];
        int4 r = ((const int4*)g_rank)[i];
        g_csr[g_offsets[d.x] + r.x] = s.x;
        g_csr[g_offsets[d.y] + r.y] = s.y;
        g_csr[g_offsets[d.z] + r.z] = s.z;
        g_csr[g_offsets[d.w] + r.w] = s.w;
    }
    // counts are dead after k_scan; zero them for the NEXT graph replay
    if (i < N_NODES / 4) ((int4*)g_counts)[i] = make_int4(0, 0, 0, 0);
    if (i < NUM_SCAN_BLOCKS) g_blockFlag[i] = 0;
    if (i == 0) {
        g_scanCounter = 0;
        g_offsets[N_NODES] = N_EDGES;   // sentinel for cnt computation this replay
    }
}

// ---------------- layer 1: x[N,8] -> g_hA[N,32]  (888 persistent blocks) ----
__global__ void __launch_bounds__(256, 6) k_layer1(const float* __restrict__ x,
                                                   const float* __restrict__ Wl,
                                                   const float* __restrict__ bl,
                                                   const float* __restrict__ Wr) {
    __shared__ float Wls[DIN * H], Wrs[DIN * H], bls[H];
    __shared__ float4 msm4[8][2];
    __shared__ float  xsm[8][8];
    for (int i = threadIdx.x; i < DIN * H; i += blockDim.x) {
        Wls[i] = Wl[i];
        Wrs[i] = Wr[i];
    }
    if (threadIdx.x < H) bls[threadIdx.x] = bl[threadIdx.x];
    __syncthreads();

    int lane  = threadIdx.x & 31;
    int w     = threadIdx.x >> 5;
    int gwarp = blockIdx.x * 8 + w;
    int sub = lane >> 1, q = lane & 1;
    const float4* x4 = (const float4*)x;

    for (int n = gwarp; n < N_NODES; n += L1_BLOCKS * 8) {
        int base = g_offsets[n];
        int cnt  = g_offsets[n + 1] - base;

        float4 acc = make_float4(0.f, 0.f, 0.f, 0.f);
        int s0 = (sub < cnt) ? g_csr[base + sub] : -1;
        for (int i = 0; i < cnt; i += 16) {
            int en = i + 16 + sub;
            int sn = (en < cnt) ? g_csr[base + en] : -1;
            if (s0 >= 0) {
                float4 v = __ldcg(&x4[s0 * 2 + q]);
                acc.x += v.x; acc.y += v.y; acc.z += v.z; acc.w += v.w;
            }
            s0 = sn;
        }
#pragma unroll
        for (int off = 16; off >= 2; off >>= 1) {
            acc.x += __shfl_down_sync(FULL, acc.x, off);
            acc.y += __shfl_down_sync(FULL, acc.y, off);
            acc.z += __shfl_down_sync(FULL, acc.z, off);
            acc.w += __shfl_down_sync(FULL, acc.w, off);
        }
        float inv = 1.f / fmaxf((float)cnt, 1.f);
        if (lane < 2) {
            msm4[w][lane] = make_float4(acc.x * inv, acc.y * inv, acc.z * inv, acc.w * inv);
        }
        if (lane < 8) xsm[w][lane] = __ldcg(&x[n * DIN + lane]);
        __syncwarp();

        const float* ms = (const float*)msm4[w];
        float o = bls[lane];
#pragma unroll
        for (int k = 0; k < DIN; k++) {
            o += ms[k] * Wls[k * H + lane] + xsm[w][k] * Wrs[k * H + lane];
        }
        __stcg(&g_hA[n * H + lane], fmaxf(o, 0.f));
        __syncwarp();
    }
}

// ---------------- gather + mean for one node (lean R6 loop) ------------------
// lane = sub*8+q ; writes mean (as 8 float4) into msDst, returns nothing else
__device__ __forceinline__ void gather_mean(const float4* __restrict__ h4,
                                            int base, int cnt,
                                            int sub, int q, int lane,
                                            float4* msDst) {
    float4 acc = make_float4(0.f, 0.f, 0.f, 0.f);
    int s0 = (sub < cnt) ? g_csr[base + sub] : -1;
    for (int i = 0; i < cnt; i += 4) {
        int en = i + 4 + sub;
        int sn = (en < cnt) ? g_csr[base + en] : -1;
        if (s0 >= 0) {
            float4 v = __ldcg(&h4[s0 * 8 + q]);
            acc.x += v.x; acc.y += v.y; acc.z += v.z; acc.w += v.w;
        }
        s0 = sn;
    }
#pragma unroll
    for (int off = 16; off >= 8; off >>= 1) {
        acc.x += __shfl_down_sync(FULL, acc.x, off);
        acc.y += __shfl_down_sync(FULL, acc.y, off);
        acc.z += __shfl_down_sync(FULL, acc.z, off);
        acc.w += __shfl_down_sync(FULL, acc.w, off);
    }
    float inv = 1.f / fmaxf((float)cnt, 1.f);
    if (lane < 8) {
        msDst[lane] = make_float4(acc.x * inv, acc.y * inv, acc.z * inv, acc.w * inv);
    }
}

// ---------------- layer 2: g_hA -> g_hB  (pair-per-warp, fused epilogue) -----
__global__ void __launch_bounds__(256) k_layer2(const float* __restrict__ Wl,
                                                const float* __restrict__ bl,
                                                const float* __restrict__ Wr) {
    __shared__ float wlT[H * WPAD], wrT[H * WPAD], bls[H];
    __shared__ float4 msA4[8][8], msB4[8][8], hsA4[8][8], hsB4[8][8];
    for (int i = threadIdx.x; i < H * H; i += blockDim.x) {
        int k = i >> 5, c = i & 31;
        wlT[c * WPAD + k] = Wl[i];
        wrT[c * WPAD + k] = Wr[i];
    }
    if (threadIdx.x < H) bls[threadIdx.x] = bl[threadIdx.x];
    __syncthreads();

    int lane  = threadIdx.x & 31;
    int w     = threadIdx.x >> 5;
    int gwarp = blockIdx.x * 8 + w;
    int sub = lane >> 3, q = lane & 7;
    const float4* h4 = (const float4*)g_hA;

    for (int p = gwarp; p < N_PAIRS; p += L23_BLOCKS * 8) {
        int nA = 2 * p, nB = 2 * p + 1;
        int baseA = g_offsets[nA];
        int baseB = g_offsets[nB];              // == offsets[nA+1]
        int endB  = g_offsets[nB + 1];
        int cntA = baseB - baseA;
        int cntB = endB - baseB;

        gather_mean(h4, baseA, cntA, sub, q, lane, msA4[w]);
        gather_mean(h4, baseB, cntB, sub, q, lane, msB4[w]);
        float hvA = __ldcg(&g_hA[nA * H + lane]);
        float hvB = __ldcg(&g_hA[nB * H + lane]);
        ((float*)hsA4[w])[lane] = hvA;
        ((float*)hsB4[w])[lane] = hvB;
        __syncwarp();

        const float4* wl4 = (const float4*)(wlT + lane * WPAD);
        const float4* wr4 = (const float4*)(wrT + lane * WPAD);
        float oA = bls[lane], oB = oA;
#pragma unroll
        for (int kk = 0; kk < 8; kk++) {
            float4 a4 = wl4[kk];                 // one weight load feeds BOTH nodes
            float4 b4 = wr4[kk];
            float4 mA = msA4[w][kk], vA = hsA4[w][kk];
            float4 mB = msB4[w][kk], vB = hsB4[w][kk];
            oA += mA.x * a4.x + mA.y * a4.y + mA.z * a4.z + mA.w * a4.w;
            oA += vA.x * b4.x + vA.y * b4.y + vA.z * b4.z + vA.w * b4.w;
            oB += mB.x * a4.x + mB.y * a4.y + mB.z * a4.z + mB.w * a4.w;
            oB += vB.x * b4.x + vB.y * b4.y + vB.z * b4.z + vB.w * b4.w;
        }
        __stcg(&g_hB[nA * H + lane], fmaxf(oA, 0.f));
        __stcg(&g_hB[nB * H + lane], fmaxf(oB, 0.f));
        __syncwarp();
    }
}

// ---------------- layer 3 + MLP head (pair-per-warp, fused epilogue) ---------
__global__ void __launch_bounds__(256) k_layer3_head(float* __restrict__ out,
                                                     const float* __restrict__ Wl,
                                                     const float* __restrict__ bl,
                                                     const float* __restrict__ Wr,
                                                     const float* __restrict__ Wh1,
                                                     const float* __restrict__ bh1,
                                                     const float* __restrict__ Wh2,
                                                     const float* __restrict__ bh2) {
    __shared__ float wlT[H * WPAD], wrT[H * WPAD], w1T[H * WPAD];
    __shared__ float bls[H], b1s[H], W2s[H * 3], b2s[3];
    __shared__ float4 msA4[8][8], msB4[8][8], hsA4[8][8], hsB4[8][8];
    for (int i = threadIdx.x; i < H * H; i += blockDim.x) {
        int k = i >> 5, c = i & 31;
        wlT[c * WPAD + k] = Wl[i];
        wrT[c * WPAD + k] = Wr[i];
        w1T[c * WPAD + k] = Wh1[i];
    }
    if (threadIdx.x < H) {
        bls[threadIdx.x] = bl[threadIdx.x];
        b1s[threadIdx.x] = bh1[threadIdx.x];
    }
    for (int i = threadIdx.x; i < H * 3; i += blockDim.x) W2s[i] = Wh2[i];
    if (threadIdx.x < 3) b2s[threadIdx.x] = bh2[threadIdx.x];
    __syncthreads();

    int lane  = threadIdx.x & 31;
    int w     = threadIdx.x >> 5;
    int gwarp = blockIdx.x * 8 + w;
    int sub = lane >> 3, q = lane & 7;
    const float4* h4 = (const float4*)g_hB;

    for (int p = gwarp; p < N_PAIRS; p += L23_BLOCKS * 8) {
        int nA = 2 * p, nB = 2 * p + 1;
        int baseA = g_offsets[nA];
        int baseB = g_offsets[nB];
        int endB  = g_offsets[nB + 1];
        int cntA = baseB - baseA;
        int cntB = endB - baseB;

        gather_mean(h4, baseA, cntA, sub, q, lane, msA4[w]);
        gather_mean(h4, baseB, cntB, sub, q, lane, msB4[w]);
        float hvA = __ldcg(&g_hB[nA * H + lane]);
        float hvB = __ldcg(&g_hB[nB * H + lane]);
        ((float*)hsA4[w])[lane] = hvA;
        ((float*)hsB4[w])[lane] = hvB;
        __syncwarp();

        const float4* wl4 = (const float4*)(wlT + lane * WPAD);
        const float4* wr4 = (const float4*)(wrT + lane * WPAD);
        float oA = bls[lane], oB = oA;
#pragma unroll
        for (int kk = 0; kk < 8; kk++) {
            float4 a4 = wl4[kk];
            float4 b4 = wr4[kk];
            float4 mA = msA4[w][kk], vA = hsA4[w][kk];
            float4 mB = msB4[w][kk], vB = hsB4[w][kk];
            oA += mA.x * a4.x + mA.y * a4.y + mA.z * a4.z + mA.w * a4.w;
            oA += vA.x * b4.x + vA.y * b4.y + vA.z * b4.z + vA.w * b4.w;
            oB += mB.x * a4.x + mB.y * a4.y + mB.z * a4.z + mB.w * a4.w;
            oB += vB.x * b4.x + vB.y * b4.y + vB.z * b4.z + vB.w * b4.w;
        }
        float h3A = fmaxf(oA, 0.f);
        float h3B = fmaxf(oB, 0.f);

        // head layer 1: 32 -> 32, relu (reuse hs buffers for h3 broadcast)
        __syncwarp();
        ((float*)hsA4[w])[lane] = h3A;
        ((float*)hsB4[w])[lane] = h3B;
        __syncwarp();
        const float4* w14 = (const float4*)(w1T + lane * WPAD);
        float t1A = b1s[lane], t1B = t1A;
#pragma unroll
        for (int kk = 0; kk < 8; kk++) {
            float4 a4 = w14[kk];
            float4 vA = hsA4[w][kk];
            float4 vB = hsB4[w][kk];
            t1A += vA.x * a4.x + vA.y * a4.y + vA.z * a4.z + vA.w * a4.w;
            t1B += vB.x * a4.x + vB.y * a4.y + vB.z * a4.z + vB.w * a4.w;
        }
        t1A = fmaxf(t1A, 0.f);
        t1B = fmaxf(t1B, 0.f);

        // head layer 2: 32 -> 3, warp reductions for both nodes
        float w0 = W2s[lane * 3 + 0], w1 = W2s[lane * 3 + 1], w2 = W2s[lane * 3 + 2];
        float pA0 = t1A * w0, pA1 = t1A * w1, pA2 = t1A * w2;
        float pB0 = t1B * w0, pB1 = t1B * w1, pB2 = t1B * w2;
#pragma unroll
        for (int off = 16; off > 0; off >>= 1) {
            pA0 += __shfl_xor_sync(FULL, pA0, off);
            pA1 += __shfl_xor_sync(FULL, pA1, off);
            pA2 += __shfl_xor_sync(FULL, pA2, off);
            pB0 += __shfl_xor_sync(FULL, pB0, off);
            pB1 += __shfl_xor_sync(FULL, pB1, off);
            pB2 += __shfl_xor_sync(FULL, pB2, off);
        }
        if (lane == 0) {
            out[nA * 3 + 0] = pA0 + b2s[0];
            out[nA * 3 + 1] = pA1 + b2s[1];
            out[nA * 3 + 2] = pA2 + b2s[2];
            out[nB * 3 + 0] = pB0 + b2s[0];
            out[nB * 3 + 1] = pB1 + b2s[1];
            out[nB * 3 + 2] = pB2 + b2s[2];
        }
        __syncwarp();
    }
}

// ---------------- launcher ---------------------------------------------------
extern "C" void kernel_launch(void* const* d_in, const int* in_sizes, int n_in,
                              void* d_out, int out_size) {
    const float* x   = (const float*)d_in[0];
    const int*   ei  = (const int*)d_in[1];    // int64 in reference -> int32 on device
    const int*   src = ei;
    const int*   dst = ei + N_EDGES;
    const float* Wl1 = (const float*)d_in[2];
    const float* bl1 = (const float*)d_in[3];
    const float* Wr1 = (const float*)d_in[4];
    const float* Wl2 = (const float*)d_in[5];
    const float* bl2 = (const float*)d_in[6];
    const float* Wr2 = (const float*)d_in[7];
    const float* Wl3 = (const float*)d_in[8];
    const float* bl3 = (const float*)d_in[9];
    const float* Wr3 = (const float*)d_in[10];
    const float* Wh1 = (const float*)d_in[11];
    const float* bh1 = (const float*)d_in[12];
    const float* Wh2 = (const float*)d_in[13];
    const float* bh2 = (const float*)d_in[14];
    float* out = (float*)d_out;

    k_hist<<<(N_EDGES / 4 + 255) / 256, 256>>>(dst);
    k_scan<<<NUM_SCAN_BLOCKS, 512>>>();
    k_fill<<<(N_EDGES / 4 + 255) / 256, 256>>>(src, dst);

    k_layer1<<<L1_BLOCKS, 256>>>(x, Wl1, bl1, Wr1);
    k_layer2<<<L23_BLOCKS, 256>>>(Wl2, bl2, Wr2);
    k_layer3_head<<<L23_BLOCKS, 256>>>(out, Wl3, bl3, Wr3, Wh1, bh1, Wh2, bh2);
}

// round 12
// speedup vs baseline: 1.1484x; 1.0222x over previous
#include <cuda_runtime.h>

#define N_NODES 100000
#define N_PAIRS (N_NODES / 2)
#define N_QUADS (N_NODES / 4)
#define N_EDGES 1600000
#define DIN 8
#define H 32
#define WPAD 36            // padded transposed-weight row stride (floats)
#define FULL 0xffffffffu

#define SCAN_ELEMS 2048
#define NUM_SCAN_BLOCKS ((N_NODES + SCAN_ELEMS - 1) / SCAN_ELEMS)   // 49
#define L1_BLOCKS  888     // layer1: 6 blocks/SM (measured best)
#define L23_BLOCKS 592     // layers 2/3: 4 blocks/SM (measured best)

// ---------------- scratch (device globals; no allocation allowed) ----------
__device__ int   g_counts[N_NODES];
__device__ int   g_offsets[N_NODES + 1];
__device__ int   g_rank[N_EDGES];
__device__ int   g_csr[N_EDGES];
__device__ float g_hA[N_NODES * H];
__device__ float g_hB[N_NODES * H];
__device__ int   g_blockAgg[NUM_SCAN_BLOCKS];
__device__ int   g_blockPrefix[NUM_SCAN_BLOCKS];
__device__ int   g_blockFlag[NUM_SCAN_BLOCKS];   // 0=none 1=agg 2=prefix
__device__ int   g_scanCounter;

// ---------------- hist (counts pre-zeroed by previous replay's k_fill) ------
__global__ void k_hist(const int* __restrict__ dst) {
    int i = blockIdx.x * blockDim.x + threadIdx.x;
    if (i < N_EDGES / 4) {
        int4 d = ((const int4*)dst)[i];
        int4 r;
        r.x = atomicAdd(&g_counts[d.x], 1);
        r.y = atomicAdd(&g_counts[d.y], 1);
        r.z = atomicAdd(&g_counts[d.z], 1);
        r.w = atomicAdd(&g_counts[d.w], 1);
        ((int4*)g_rank)[i] = r;
    }
}

// ---------------- single-pass decoupled-lookback exclusive scan --------------
__global__ void __launch_bounds__(512) k_scan() {
    __shared__ int s_warpSums[16];
    __shared__ int s_bid;
    __shared__ int s_exclBase;

    int t = threadIdx.x;
    if (t == 0) s_bid = atomicAdd(&g_scanCounter, 1);
    __syncthreads();
    int bid  = s_bid;
    int base = bid * SCAN_ELEMS;
    int idx  = base + t * 4;
    int lane = t & 31, wid = t >> 5;

    int4 v;
    if (idx + 3 < N_NODES) {
        v = ((const int4*)g_counts)[idx >> 2];
    } else {
        v.x = (idx + 0 < N_NODES) ? g_counts[idx + 0] : 0;
        v.y = (idx + 1 < N_NODES) ? g_counts[idx + 1] : 0;
        v.z = (idx + 2 < N_NODES) ? g_counts[idx + 2] : 0;
        v.w = (idx + 3 < N_NODES) ? g_counts[idx + 3] : 0;
    }
    int tsum = v.x + v.y + v.z + v.w;
    int tIncl = tsum;
#pragma unroll
    for (int off = 1; off < 32; off <<= 1) {
        int u = __shfl_up_sync(FULL, tIncl, off);
        if (lane >= off) tIncl += u;
    }
    if (lane == 31) s_warpSums[wid] = tIncl;
    __syncthreads();

    if (t == 0) {
        int run = 0;
#pragma unroll
        for (int i = 0; i < 16; i++) { int a = s_warpSums[i]; s_warpSums[i] = run; run += a; }
        if (bid == 0) {
            g_blockPrefix[0] = run;
            __threadfence();
            ((volatile int*)g_blockFlag)[0] = 2;
            s_exclBase = 0;
        } else {
            g_blockAgg[bid] = run;
            __threadfence();
            ((volatile int*)g_blockFlag)[bid] = 1;
            int running = 0;
            int j = bid - 1;
            while (true) {
                int f;
                while ((f = ((volatile int*)g_blockFlag)[j]) == 0) { }
                __threadfence();
                if (f == 2) { running += ((volatile int*)g_blockPrefix)[j]; break; }
                running += ((volatile int*)g_blockAgg)[j];
                j--;
            }
            g_blockPrefix[bid] = running + run;
            __threadfence();
            ((volatile int*)g_blockFlag)[bid] = 2;
            s_exclBase = running;
        }
    }
    __syncthreads();

    int e0 = s_exclBase + s_warpSums[wid] + (tIncl - tsum);
    int4 o;
    o.x = e0;
    o.y = e0 + v.x;
    o.z = o.y + v.y;
    o.w = o.z + v.z;
    if (idx + 3 < N_NODES) {
        ((int4*)g_offsets)[idx >> 2] = o;
    } else {
        if (idx + 0 < N_NODES) g_offsets[idx + 0] = o.x;
        if (idx + 1 < N_NODES) g_offsets[idx + 1] = o.y;
        if (idx + 2 < N_NODES) g_offsets[idx + 2] = o.z;
        if (idx + 3 < N_NODES) g_offsets[idx + 3] = o.w;
    }
}

// ---------------- fill (atomic-free) + re-zero state for next replay ---------
__global__ void k_fill(const int* __restrict__ src,
                       const int* __restrict__ dst) {
    int i = blockIdx.x * blockDim.x + threadIdx.x;
    if (i < N_EDGES / 4) {
        int4 d = ((const int4*)dst)[i];
        int4 s = ((const int4*)src)[i];
        int4 r = ((const int4*)g_rank)[i];
        g_csr[g_offsets[d.x] + r.x] = s.x;
        g_csr[g_offsets[d.y] + r.y] = s.y;
        g_csr[g_offsets[d.z] + r.z] = s.z;
        g_csr[g_offsets[d.w] + r.w] = s.w;
    }
    // counts are dead after k_scan; zero them for the NEXT graph replay
    if (i < N_NODES / 4) ((int4*)g_counts)[i] = make_int4(0, 0, 0, 0);
    if (i < NUM_SCAN_BLOCKS) g_blockFlag[i] = 0;
    if (i == 0) {
        g_scanCounter = 0;
        g_offsets[N_NODES] = N_EDGES;   // sentinel for cnt computation this replay
    }
}

// ---------------- layer1 gather helper (16 edges/iter, 8-dim rows) ----------
__device__ __forceinline__ void gather_mean8(const float4* __restrict__ x4,
                                             int base, int cnt,
                                             int sub, int q, int lane,
                                             float* msDst /* 8 floats */) {
    float4 acc = make_float4(0.f, 0.f, 0.f, 0.f);
    int s0 = (sub < cnt) ? g_csr[base + sub] : -1;
    for (int i = 0; i < cnt; i += 16) {
        int en = i + 16 + sub;
        int sn = (en < cnt) ? g_csr[base + en] : -1;
        if (s0 >= 0) {
            float4 v = __ldcg(&x4[s0 * 2 + q]);
            acc.x += v.x; acc.y += v.y; acc.z += v.z; acc.w += v.w;
        }
        s0 = sn;
    }
#pragma unroll
    for (int off = 16; off >= 2; off >>= 1) {
        acc.x += __shfl_down_sync(FULL, acc.x, off);
        acc.y += __shfl_down_sync(FULL, acc.y, off);
        acc.z += __shfl_down_sync(FULL, acc.z, off);
        acc.w += __shfl_down_sync(FULL, acc.w, off);
    }
    float inv = 1.f / fmaxf((float)cnt, 1.f);
    if (lane < 2) {
        ((float4*)msDst)[lane] = make_float4(acc.x * inv, acc.y * inv, acc.z * inv, acc.w * inv);
    }
}

// ---------------- layer 1: x[N,8] -> g_hA[N,32]  (pair-per-warp) ------------
__global__ void __launch_bounds__(256, 6) k_layer1(const float* __restrict__ x,
                                                   const float* __restrict__ Wl,
                                                   const float* __restrict__ bl,
                                                   const float* __restrict__ Wr) {
    __shared__ float Wls[DIN * H], Wrs[DIN * H], bls[H];
    __shared__ float msA[8][8], msB[8][8];
    __shared__ float xsA[8][8], xsB[8][8];
    for (int i = threadIdx.x; i < DIN * H; i += blockDim.x) {
        Wls[i] = Wl[i];
        Wrs[i] = Wr[i];
    }
    if (threadIdx.x < H) bls[threadIdx.x] = bl[threadIdx.x];
    __syncthreads();

    int lane  = threadIdx.x & 31;
    int w     = threadIdx.x >> 5;
    int gwarp = blockIdx.x * 8 + w;
    int sub = lane >> 1, q = lane & 1;
    const float4* x4 = (const float4*)x;

    for (int p = gwarp; p < N_PAIRS; p += L1_BLOCKS * 8) {
        int nA = 2 * p, nB = 2 * p + 1;
        int baseA = g_offsets[nA];
        int baseB = g_offsets[nB];
        int endB  = g_offsets[nB + 1];
        int cntA = baseB - baseA;
        int cntB = endB - baseB;

        gather_mean8(x4, baseA, cntA, sub, q, lane, msA[w]);
        gather_mean8(x4, baseB, cntB, sub, q, lane, msB[w]);
        if (lane < 8) {
            xsA[w][lane] = __ldcg(&x[nA * DIN + lane]);
            xsB[w][lane] = __ldcg(&x[nB * DIN + lane]);
        }
        __syncwarp();

        float oA = bls[lane], oB = oA;
#pragma unroll
        for (int k = 0; k < DIN; k++) {
            float wl = Wls[k * H + lane];        // one weight load, two nodes
            float wr = Wrs[k * H + lane];
            oA += msA[w][k] * wl + xsA[w][k] * wr;
            oB += msB[w][k] * wl + xsB[w][k] * wr;
        }
        __stcg(&g_hA[nA * H + lane], fmaxf(oA, 0.f));
        __stcg(&g_hA[nB * H + lane], fmaxf(oB, 0.f));
        __syncwarp();
    }
}

// ---------------- gather + mean for one node (lean, 32-dim rows) -------------
__device__ __forceinline__ void gather_mean(const float4* __restrict__ h4,
                                            int base, int cnt,
                                            int sub, int q, int lane,
                                            float4* msDst) {
    float4 acc = make_float4(0.f, 0.f, 0.f, 0.f);
    int s0 = (sub < cnt) ? g_csr[base + sub] : -1;
    for (int i = 0; i < cnt; i += 4) {
        int en = i + 4 + sub;
        int sn = (en < cnt) ? g_csr[base + en] : -1;
        if (s0 >= 0) {
            float4 v = __ldcg(&h4[s0 * 8 + q]);
            acc.x += v.x; acc.y += v.y; acc.z += v.z; acc.w += v.w;
        }
        s0 = sn;
    }
#pragma unroll
    for (int off = 16; off >= 8; off >>= 1) {
        acc.x += __shfl_down_sync(FULL, acc.x, off);
        acc.y += __shfl_down_sync(FULL, acc.y, off);
        acc.z += __shfl_down_sync(FULL, acc.z, off);
        acc.w += __shfl_down_sync(FULL, acc.w, off);
    }
    float inv = 1.f / fmaxf((float)cnt, 1.f);
    if (lane < 8) {
        msDst[lane] = make_float4(acc.x * inv, acc.y * inv, acc.z * inv, acc.w * inv);
    }
}

// ---------------- layer 2: g_hA -> g_hB  (QUAD-per-warp, fused epilogue) -----
__global__ void __launch_bounds__(256) k_layer2(const float* __restrict__ Wl,
                                                const float* __restrict__ bl,
                                                const float* __restrict__ Wr) {
    __shared__ float wlT[H * WPAD], wrT[H * WPAD], bls[H];
    __shared__ float4 ms4[4][8][8], hs4[4][8][8];
    for (int i = threadIdx.x; i < H * H; i += blockDim.x) {
        int k = i >> 5, c = i & 31;
        wlT[c * WPAD + k] = Wl[i];
        wrT[c * WPAD + k] = Wr[i];
    }
    if (threadIdx.x < H) bls[threadIdx.x] = bl[threadIdx.x];
    __syncthreads();

    int lane  = threadIdx.x & 31;
    int w     = threadIdx.x >> 5;
    int gwarp = blockIdx.x * 8 + w;
    int sub = lane >> 3, q = lane & 7;
    const float4* h4 = (const float4*)g_hA;

    for (int p = gwarp; p < N_QUADS; p += L23_BLOCKS * 8) {
        int n0 = 4 * p;
        int off0 = g_offsets[n0];
        int off1 = g_offsets[n0 + 1];
        int off2 = g_offsets[n0 + 2];
        int off3 = g_offsets[n0 + 3];
        int off4 = g_offsets[n0 + 4];

        gather_mean(h4, off0, off1 - off0, sub, q, lane, ms4[0][w]);
        gather_mean(h4, off1, off2 - off1, sub, q, lane, ms4[1][w]);
        gather_mean(h4, off2, off3 - off2, sub, q, lane, ms4[2][w]);
        gather_mean(h4, off3, off4 - off3, sub, q, lane, ms4[3][w]);
#pragma unroll
        for (int j = 0; j < 4; j++) {
            ((float*)hs4[j][w])[lane] = __ldcg(&g_hA[(n0 + j) * H + lane]);
        }
        __syncwarp();

        const float4* wl4 = (const float4*)(wlT + lane * WPAD);
        const float4* wr4 = (const float4*)(wrT + lane * WPAD);
        float o0 = bls[lane], o1 = o0, o2 = o0, o3 = o0;
#pragma unroll
        for (int kk = 0; kk < 8; kk++) {
            float4 a4 = wl4[kk];                 // one weight load feeds FOUR nodes
            float4 b4 = wr4[kk];
            float4 m0 = ms4[0][w][kk], v0 = hs4[0][w][kk];
            float4 m1 = ms4[1][w][kk], v1 = hs4[1][w][kk];
            float4 m2 = ms4[2][w][kk], v2 = hs4[2][w][kk];
            float4 m3 = ms4[3][w][kk], v3 = hs4[3][w][kk];
            o0 += m0.x * a4.x + m0.y * a4.y + m0.z * a4.z + m0.w * a4.w
                + v0.x * b4.x + v0.y * b4.y + v0.z * b4.z + v0.w * b4.w;
            o1 += m1.x * a4.x + m1.y * a4.y + m1.z * a4.z + m1.w * a4.w
                + v1.x * b4.x + v1.y * b4.y + v1.z * b4.z + v1.w * b4.w;
            o2 += m2.x * a4.x + m2.y * a4.y + m2.z * a4.z + m2.w * a4.w
                + v2.x * b4.x + v2.y * b4.y + v2.z * b4.z + v2.w * b4.w;
            o3 += m3.x * a4.x + m3.y * a4.y + m3.z * a4.z + m3.w * a4.w
                + v3.x * b4.x + v3.y * b4.y + v3.z * b4.z + v3.w * b4.w;
        }
        __stcg(&g_hB[(n0 + 0) * H + lane], fmaxf(o0, 0.f));
        __stcg(&g_hB[(n0 + 1) * H + lane], fmaxf(o1, 0.f));
        __stcg(&g_hB[(n0 + 2) * H + lane], fmaxf(o2, 0.f));
        __stcg(&g_hB[(n0 + 3) * H + lane], fmaxf(o3, 0.f));
        __syncwarp();
    }
}

// ---------------- layer 3 + MLP head (pair-per-warp, fused epilogue) ---------
__global__ void __launch_bounds__(256) k_layer3_head(float* __restrict__ out,
                                                     const float* __restrict__ Wl,
                                                     const float* __restrict__ bl,
                                                     const float* __restrict__ Wr,
                                                     const float* __restrict__ Wh1,
                                                     const float* __restrict__ bh1,
                                                     const float* __restrict__ Wh2,
                                                     const float* __restrict__ bh2) {
    __shared__ float wlT[H * WPAD], wrT[H * WPAD], w1T[H * WPAD];
    __shared__ float bls[H], b1s[H], W2s[H * 3], b2s[3];
    __shared__ float4 msA4[8][8], msB4[8][8], hsA4[8][8], hsB4[8][8];
    for (int i = threadIdx.x; i < H * H; i += blockDim.x) {
        int k = i >> 5, c = i & 31;
        wlT[c * WPAD + k] = Wl[i];
        wrT[c * WPAD + k] = Wr[i];
        w1T[c * WPAD + k] = Wh1[i];
    }
    if (threadIdx.x < H) {
        bls[threadIdx.x] = bl[threadIdx.x];
        b1s[threadIdx.x] = bh1[threadIdx.x];
    }
    for (int i = threadIdx.x; i < H * 3; i += blockDim.x) W2s[i] = Wh2[i];
    if (threadIdx.x < 3) b2s[threadIdx.x] = bh2[threadIdx.x];
    __syncthreads();

    int lane  = threadIdx.x & 31;
    int w     = threadIdx.x >> 5;
    int gwarp = blockIdx.x * 8 + w;
    int sub = lane >> 3, q = lane & 7;
    const float4* h4 = (const float4*)g_hB;

    for (int p = gwarp; p < N_PAIRS; p += L23_BLOCKS * 8) {
        int nA = 2 * p, nB = 2 * p + 1;
        int baseA = g_offsets[nA];
        int baseB = g_offsets[nB];
        int endB  = g_offsets[nB + 1];
        int cntA = baseB - baseA;
        int cntB = endB - baseB;

        gather_mean(h4, baseA, cntA, sub, q, lane, msA4[w]);
        gather_mean(h4, baseB, cntB, sub, q, lane, msB4[w]);
        float hvA = __ldcg(&g_hB[nA * H + lane]);
        float hvB = __ldcg(&g_hB[nB * H + lane]);
        ((float*)hsA4[w])[lane] = hvA;
        ((float*)hsB4[w])[lane] = hvB;
        __syncwarp();

        const float4* wl4 = (const float4*)(wlT + lane * WPAD);
        const float4* wr4 = (const float4*)(wrT + lane * WPAD);
        float oA = bls[lane], oB = oA;
#pragma unroll
        for (int kk = 0; kk < 8; kk++) {
            float4 a4 = wl4[kk];
            float4 b4 = wr4[kk];
            float4 mA = msA4[w][kk], vA = hsA4[w][kk];
            float4 mB = msB4[w][kk], vB = hsB4[w][kk];
            oA += mA.x * a4.x + mA.y * a4.y + mA.z * a4.z + mA.w * a4.w;
            oA += vA.x * b4.x + vA.y * b4.y + vA.z * b4.z + vA.w * b4.w;
            oB += mB.x * a4.x + mB.y * a4.y + mB.z * a4.z + mB.w * a4.w;
            oB += vB.x * b4.x + vB.y * b4.y + vB.z * b4.z + vB.w * b4.w;
        }
        float h3A = fmaxf(oA, 0.f);
        float h3B = fmaxf(oB, 0.f);

        // head layer 1: 32 -> 32, relu (reuse hs buffers for h3 broadcast)
        __syncwarp();
        ((float*)hsA4[w])[lane] = h3A;
        ((float*)hsB4[w])[lane] = h3B;
        __syncwarp();
        const float4* w14 = (const float4*)(w1T + lane * WPAD);
        float t1A = b1s[lane], t1B = t1A;
#pragma unroll
        for (int kk = 0; kk < 8; kk++) {
            float4 a4 = w14[kk];
            float4 vA = hsA4[w][kk];
            float4 vB = hsB4[w][kk];
            t1A += vA.x * a4.x + vA.y * a4.y + vA.z * a4.z + vA.w * a4.w;
            t1B += vB.x * a4.x + vB.y * a4.y + vB.z * a4.z + vB.w * a4.w;
        }
        t1A = fmaxf(t1A, 0.f);
        t1B = fmaxf(t1B, 0.f);

        // head layer 2: 32 -> 3, warp reductions for both nodes
        float w0 = W2s[lane * 3 + 0], w1 = W2s[lane * 3 + 1], w2 = W2s[lane * 3 + 2];
        float pA0 = t1A * w0, pA1 = t1A * w1, pA2 = t1A * w2;
        float pB0 = t1B * w0, pB1 = t1B * w1, pB2 = t1B * w2;
#pragma unroll
        for (int off = 16; off > 0; off >>= 1) {
            pA0 += __shfl_xor_sync(FULL, pA0, off);
            pA1 += __shfl_xor_sync(FULL, pA1, off);
            pA2 += __shfl_xor_sync(FULL, pA2, off);
            pB0 += __shfl_xor_sync(FULL, pB0, off);
            pB1 += __shfl_xor_sync(FULL, pB1, off);
            pB2 += __shfl_xor_sync(FULL, pB2, off);
        }
        if (lane == 0) {
            out[nA * 3 + 0] = pA0 + b2s[0];
            out[nA * 3 + 1] = pA1 + b2s[1];
            out[nA * 3 + 2] = pA2 + b2s[2];
            out[nB * 3 + 0] = pB0 + b2s[0];
            out[nB * 3 + 1] = pB1 + b2s[1];
            out[nB * 3 + 2] = pB2 + b2s[2];
        }
        __syncwarp();
    }
}

// ---------------- launcher ---------------------------------------------------
extern "C" void kernel_launch(void* const* d_in, const int* in_sizes, int n_in,
                              void* d_out, int out_size) {
    const float* x   = (const float*)d_in[0];
    const int*   ei  = (const int*)d_in[1];    // int64 in reference -> int32 on device
    const int*   src = ei;
    const int*   dst = ei + N_EDGES;
    const float* Wl1 = (const float*)d_in[2];
    const float* bl1 = (const float*)d_in[3];
    const float* Wr1 = (const float*)d_in[4];
    const float* Wl2 = (const float*)d_in[5];
    const float* bl2 = (const float*)d_in[6];
    const float* Wr2 = (const float*)d_in[7];
    const float* Wl3 = (const float*)d_in[8];
    const float* bl3 = (const float*)d_in[9];
    const float* Wr3 = (const float*)d_in[10];
    const float* Wh1 = (const float*)d_in[11];
    const float* bh1 = (const float*)d_in[12];
    const float* Wh2 = (const float*)d_in[13];
    const float* bh2 = (const float*)d_in[14];
    float* out = (float*)d_out;

    k_hist<<<(N_EDGES / 4 + 255) / 256, 256>>>(dst);
    k_scan<<<NUM_SCAN_BLOCKS, 512>>>();
    k_fill<<<(N_EDGES / 4 + 255) / 256, 256>>>(src, dst);

    k_layer1<<<L1_BLOCKS, 256>>>(x, Wl1, bl1, Wr1);
    k_layer2<<<L23_BLOCKS, 256>>>(Wl2, bl2, Wr2);
    k_layer3_head<<<L23_BLOCKS, 256>>>(out, Wl3, bl3, Wr3, Wh1, bh1, Wh2, bh2);
}

// round 13
// speedup vs baseline: 1.1891x; 1.0354x over previous
#include <cuda_runtime.h>

#define N_NODES 100000
#define N_QUADS (N_NODES / 4)
#define N_EDGES 1600000
#define DIN 8
#define H 32
#define WPAD 36            // padded transposed-weight row stride (floats)
#define FULL 0xffffffffu

#define SCAN_ELEMS 2048
#define NUM_SCAN_BLOCKS ((N_NODES + SCAN_ELEMS - 1) / SCAN_ELEMS)   // 49
#define L1_BLOCKS  888     // layer1: 6 blocks/SM (measured best)
#define L23_BLOCKS 592     // layers 2/3: 4 blocks/SM (measured best)

// ---------------- scratch (device globals; no allocation allowed) ----------
__device__ int   g_counts[N_NODES];
__device__ int   g_offsets[N_NODES + 1];
__device__ int   g_rank[N_EDGES];
__device__ int   g_csr[N_EDGES];
__device__ float g_hA[N_NODES * H];
__device__ float g_hB[N_NODES * H];
__device__ int   g_blockAgg[NUM_SCAN_BLOCKS];
__device__ int   g_blockPrefix[NUM_SCAN_BLOCKS];
__device__ int   g_blockFlag[NUM_SCAN_BLOCKS];   // 0=none 1=agg 2=prefix
__device__ int   g_scanCounter;

// ---------------- hist (counts pre-zeroed by previous replay's k_fill) ------
__global__ void k_hist(const int* __restrict__ dst) {
    int i = blockIdx.x * blockDim.x + threadIdx.x;
    if (i < N_EDGES / 4) {
        int4 d = ((const int4*)dst)[i];
        int4 r;
        r.x = atomicAdd(&g_counts[d.x], 1);
        r.y = atomicAdd(&g_counts[d.y], 1);
        r.z = atomicAdd(&g_counts[d.z], 1);
        r.w = atomicAdd(&g_counts[d.w], 1);
        ((int4*)g_rank)[i] = r;
    }
}

// ---------------- single-pass decoupled-lookback exclusive scan --------------
__global__ void __launch_bounds__(512) k_scan() {
    __shared__ int s_warpSums[16];
    __shared__ int s_bid;
    __shared__ int s_exclBase;

    int t = threadIdx.x;
    if (t == 0) s_bid = atomicAdd(&g_scanCounter, 1);
    __syncthreads();
    int bid  = s_bid;
    int base = bid * SCAN_ELEMS;
    int idx  = base + t * 4;
    int lane = t & 31, wid = t >> 5;

    int4 v;
    if (idx + 3 < N_NODES) {
        v = ((const int4*)g_counts)[idx >> 2];
    } else {
        v.x = (idx + 0 < N_NODES) ? g_counts[idx + 0] : 0;
        v.y = (idx + 1 < N_NODES) ? g_counts[idx + 1] : 0;
        v.z = (idx + 2 < N_NODES) ? g_counts[idx + 2] : 0;
        v.w = (idx + 3 < N_NODES) ? g_counts[idx + 3] : 0;
    }
    int tsum = v.x + v.y + v.z + v.w;
    int tIncl = tsum;
#pragma unroll
    for (int off = 1; off < 32; off <<= 1) {
        int u = __shfl_up_sync(FULL, tIncl, off);
        if (lane >= off) tIncl += u;
    }
    if (lane == 31) s_warpSums[wid] = tIncl;
    __syncthreads();

    if (t == 0) {
        int run = 0;
#pragma unroll
        for (int i = 0; i < 16; i++) { int a = s_warpSums[i]; s_warpSums[i] = run; run += a; }
        if (bid == 0) {
            g_blockPrefix[0] = run;
            __threadfence();
            ((volatile int*)g_blockFlag)[0] = 2;
            s_exclBase = 0;
        } else {
            g_blockAgg[bid] = run;
            __threadfence();
            ((volatile int*)g_blockFlag)[bid] = 1;
            int running = 0;
            int j = bid - 1;
            while (true) {
                int f;
                while ((f = ((volatile int*)g_blockFlag)[j]) == 0) { }
                __threadfence();
                if (f == 2) { running += ((volatile int*)g_blockPrefix)[j]; break; }
                running += ((volatile int*)g_blockAgg)[j];
                j--;
            }
            g_blockPrefix[bid] = running + run;
            __threadfence();
            ((volatile int*)g_blockFlag)[bid] = 2;
            s_exclBase = running;
        }
    }
    __syncthreads();

    int e0 = s_exclBase + s_warpSums[wid] + (tIncl - tsum);
    int4 o;
    o.x = e0;
    o.y = e0 + v.x;
    o.z = o.y + v.y;
    o.w = o.z + v.z;
    if (idx + 3 < N_NODES) {
        ((int4*)g_offsets)[idx >> 2] = o;
    } else {
        if (idx + 0 < N_NODES) g_offsets[idx + 0] = o.x;
        if (idx + 1 < N_NODES) g_offsets[idx + 1] = o.y;
        if (idx + 2 < N_NODES) g_offsets[idx + 2] = o.z;
        if (idx + 3 < N_NODES) g_offsets[idx + 3] = o.w;
    }
}

// ---------------- fill (atomic-free) + re-zero state for next replay ---------
__global__ void k_fill(const int* __restrict__ src,
                       const int* __restrict__ dst) {
    int i = blockIdx.x * blockDim.x + threadIdx.x;
    if (i < N_EDGES / 4) {
        int4 d = ((const int4*)dst)[i];
        int4 s = ((const int4*)src)[i];
        int4 r = ((const int4*)g_rank)[i];
        g_csr[g_offsets[d.x] + r.x] = s.x;
        g_csr[g_offsets[d.y] + r.y] = s.y;
        g_csr[g_offsets[d.z] + r.z] = s.z;
        g_csr[g_offsets[d.w] + r.w] = s.w;
    }
    // counts are dead after k_scan; zero them for the NEXT graph replay
    if (i < N_NODES / 4) ((int4*)g_counts)[i] = make_int4(0, 0, 0, 0);
    if (i < NUM_SCAN_BLOCKS) g_blockFlag[i] = 0;
    if (i == 0) {
        g_scanCounter = 0;
        g_offsets[N_NODES] = N_EDGES;   // sentinel for cnt computation this replay
    }
}

// ---------------- layer1 gather helper (16 edges/iter, 8-dim rows) ----------
__device__ __forceinline__ void gather_mean8(const float4* __restrict__ x4,
                                             int base, int cnt,
                                             int sub, int q, int lane,
                                             float* msDst /* 8 floats */) {
    float4 acc = make_float4(0.f, 0.f, 0.f, 0.f);
    int s0 = (sub < cnt) ? g_csr[base + sub] : -1;
    for (int i = 0; i < cnt; i += 16) {
        int en = i + 16 + sub;
        int sn = (en < cnt) ? g_csr[base + en] : -1;
        if (s0 >= 0) {
            float4 v = __ldcg(&x4[s0 * 2 + q]);
            acc.x += v.x; acc.y += v.y; acc.z += v.z; acc.w += v.w;
        }
        s0 = sn;
    }
#pragma unroll
    for (int off = 16; off >= 2; off >>= 1) {
        acc.x += __shfl_down_sync(FULL, acc.x, off);
        acc.y += __shfl_down_sync(FULL, acc.y, off);
        acc.z += __shfl_down_sync(FULL, acc.z, off);
        acc.w += __shfl_down_sync(FULL, acc.w, off);
    }
    float inv = 1.f / fmaxf((float)cnt, 1.f);
    if (lane < 2) {
        ((float4*)msDst)[lane] = make_float4(acc.x * inv, acc.y * inv, acc.z * inv, acc.w * inv);
    }
}

// ---------------- layer 1: x[N,8] -> g_hA[N,32]  (QUAD-per-warp) ------------
__global__ void __launch_bounds__(256, 6) k_layer1(const float* __restrict__ x,
                                                   const float* __restrict__ Wl,
                                                   const float* __restrict__ bl,
                                                   const float* __restrict__ Wr) {
    __shared__ float Wls[DIN * H], Wrs[DIN * H], bls[H];
    __shared__ float ms[4][8][8];
    __shared__ float xs[4][8][8];
    for (int i = threadIdx.x; i < DIN * H; i += blockDim.x) {
        Wls[i] = Wl[i];
        Wrs[i] = Wr[i];
    }
    if (threadIdx.x < H) bls[threadIdx.x] = bl[threadIdx.x];
    __syncthreads();

    int lane  = threadIdx.x & 31;
    int w     = threadIdx.x >> 5;
    int gwarp = blockIdx.x * 8 + w;
    int sub = lane >> 1, q = lane & 1;
    const float4* x4 = (const float4*)x;

    for (int p = gwarp; p < N_QUADS; p += L1_BLOCKS * 8) {
        int n0 = 4 * p;
        int off0 = g_offsets[n0];
        int off1 = g_offsets[n0 + 1];
        int off2 = g_offsets[n0 + 2];
        int off3 = g_offsets[n0 + 3];
        int off4 = g_offsets[n0 + 4];

        gather_mean8(x4, off0, off1 - off0, sub, q, lane, ms[0][w]);
        gather_mean8(x4, off1, off2 - off1, sub, q, lane, ms[1][w]);
        gather_mean8(x4, off2, off3 - off2, sub, q, lane, ms[2][w]);
        gather_mean8(x4, off3, off4 - off3, sub, q, lane, ms[3][w]);
        if (lane < 8) {
#pragma unroll
            for (int j = 0; j < 4; j++) {
                xs[j][w][lane] = __ldcg(&x[(n0 + j) * DIN + lane]);
            }
        }
        __syncwarp();

        float o0 = bls[lane], o1 = o0, o2 = o0, o3 = o0;
#pragma unroll
        for (int k = 0; k < DIN; k++) {
            float wl = Wls[k * H + lane];        // one weight load, four nodes
            float wr = Wrs[k * H + lane];
            o0 += ms[0][w][k] * wl + xs[0][w][k] * wr;
            o1 += ms[1][w][k] * wl + xs[1][w][k] * wr;
            o2 += ms[2][w][k] * wl + xs[2][w][k] * wr;
            o3 += ms[3][w][k] * wl + xs[3][w][k] * wr;
        }
        __stcg(&g_hA[(n0 + 0) * H + lane], fmaxf(o0, 0.f));
        __stcg(&g_hA[(n0 + 1) * H + lane], fmaxf(o1, 0.f));
        __stcg(&g_hA[(n0 + 2) * H + lane], fmaxf(o2, 0.f));
        __stcg(&g_hA[(n0 + 3) * H + lane], fmaxf(o3, 0.f));
        __syncwarp();
    }
}

// ---------------- gather + mean for one node (lean, 32-dim rows) -------------
__device__ __forceinline__ void gather_mean(const float4* __restrict__ h4,
                                            int base, int cnt,
                                            int sub, int q, int lane,
                                            float4* msDst) {
    float4 acc = make_float4(0.f, 0.f, 0.f, 0.f);
    int s0 = (sub < cnt) ? g_csr[base + sub] : -1;
    for (int i = 0; i < cnt; i += 4) {
        int en = i + 4 + sub;
        int sn = (en < cnt) ? g_csr[base + en] : -1;
        if (s0 >= 0) {
            float4 v = __ldcg(&h4[s0 * 8 + q]);
            acc.x += v.x; acc.y += v.y; acc.z += v.z; acc.w += v.w;
        }
        s0 = sn;
    }
#pragma unroll
    for (int off = 16; off >= 8; off >>= 1) {
        acc.x += __shfl_down_sync(FULL, acc.x, off);
        acc.y += __shfl_down_sync(FULL, acc.y, off);
        acc.z += __shfl_down_sync(FULL, acc.z, off);
        acc.w += __shfl_down_sync(FULL, acc.w, off);
    }
    float inv = 1.f / fmaxf((float)cnt, 1.f);
    if (lane < 8) {
        msDst[lane] = make_float4(acc.x * inv, acc.y * inv, acc.z * inv, acc.w * inv);
    }
}

// ---------------- layer 2: g_hA -> g_hB  (QUAD-per-warp, fused epilogue) -----
__global__ void __launch_bounds__(256) k_layer2(const float* __restrict__ Wl,
                                                const float* __restrict__ bl,
                                                const float* __restrict__ Wr) {
    __shared__ float wlT[H * WPAD], wrT[H * WPAD], bls[H];
    __shared__ float4 ms4[4][8][8], hs4[4][8][8];
    for (int i = threadIdx.x; i < H * H; i += blockDim.x) {
        int k = i >> 5, c = i & 31;
        wlT[c * WPAD + k] = Wl[i];
        wrT[c * WPAD + k] = Wr[i];
    }
    if (threadIdx.x < H) bls[threadIdx.x] = bl[threadIdx.x];
    __syncthreads();

    int lane  = threadIdx.x & 31;
    int w     = threadIdx.x >> 5;
    int gwarp = blockIdx.x * 8 + w;
    int sub = lane >> 3, q = lane & 7;
    const float4* h4 = (const float4*)g_hA;

    for (int p = gwarp; p < N_QUADS; p += L23_BLOCKS * 8) {
        int n0 = 4 * p;
        int off0 = g_offsets[n0];
        int off1 = g_offsets[n0 + 1];
        int off2 = g_offsets[n0 + 2];
        int off3 = g_offsets[n0 + 3];
        int off4 = g_offsets[n0 + 4];

        gather_mean(h4, off0, off1 - off0, sub, q, lane, ms4[0][w]);
        gather_mean(h4, off1, off2 - off1, sub, q, lane, ms4[1][w]);
        gather_mean(h4, off2, off3 - off2, sub, q, lane, ms4[2][w]);
        gather_mean(h4, off3, off4 - off3, sub, q, lane, ms4[3][w]);
#pragma unroll
        for (int j = 0; j < 4; j++) {
            ((float*)hs4[j][w])[lane] = __ldcg(&g_hA[(n0 + j) * H + lane]);
        }
        __syncwarp();

        const float4* wl4 = (const float4*)(wlT + lane * WPAD);
        const float4* wr4 = (const float4*)(wrT + lane * WPAD);
        float o0 = bls[lane], o1 = o0, o2 = o0, o3 = o0;
#pragma unroll
        for (int kk = 0; kk < 8; kk++) {
            float4 a4 = wl4[kk];                 // one weight load feeds FOUR nodes
            float4 b4 = wr4[kk];
            float4 m0 = ms4[0][w][kk], v0 = hs4[0][w][kk];
            float4 m1 = ms4[1][w][kk], v1 = hs4[1][w][kk];
            float4 m2 = ms4[2][w][kk], v2 = hs4[2][w][kk];
            float4 m3 = ms4[3][w][kk], v3 = hs4[3][w][kk];
            o0 += m0.x * a4.x + m0.y * a4.y + m0.z * a4.z + m0.w * a4.w
                + v0.x * b4.x + v0.y * b4.y + v0.z * b4.z + v0.w * b4.w;
            o1 += m1.x * a4.x + m1.y * a4.y + m1.z * a4.z + m1.w * a4.w
                + v1.x * b4.x + v1.y * b4.y + v1.z * b4.z + v1.w * b4.w;
            o2 += m2.x * a4.x + m2.y * a4.y + m2.z * a4.z + m2.w * a4.w
                + v2.x * b4.x + v2.y * b4.y + v2.z * b4.z + v2.w * b4.w;
            o3 += m3.x * a4.x + m3.y * a4.y + m3.z * a4.z + m3.w * a4.w
                + v3.x * b4.x + v3.y * b4.y + v3.z * b4.z + v3.w * b4.w;
        }
        __stcg(&g_hB[(n0 + 0) * H + lane], fmaxf(o0, 0.f));
        __stcg(&g_hB[(n0 + 1) * H + lane], fmaxf(o1, 0.f));
        __stcg(&g_hB[(n0 + 2) * H + lane], fmaxf(o2, 0.f));
        __stcg(&g_hB[(n0 + 3) * H + lane], fmaxf(o3, 0.f));
        __syncwarp();
    }
}

// ---------------- layer 3 + MLP head (QUAD-per-warp, fused epilogue) ---------
__global__ void __launch_bounds__(256) k_layer3_head(float* __restrict__ out,
                                                     const float* __restrict__ Wl,
                                                     const float* __restrict__ bl,
                                                     const float* __restrict__ Wr,
                                                     const float* __restrict__ Wh1,
                                                     const float* __restrict__ bh1,
                                                     const float* __restrict__ Wh2,
                                                     const float* __restrict__ bh2) {
    __shared__ float wlT[H * WPAD], wrT[H * WPAD], w1T[H * WPAD];
    __shared__ float bls[H], b1s[H], W2s[H * 3], b2s[3];
    __shared__ float4 ms4[4][8][8], hs4[4][8][8];
    for (int i = threadIdx.x; i < H * H; i += blockDim.x) {
        int k = i >> 5, c = i & 31;
        wlT[c * WPAD + k] = Wl[i];
        wrT[c * WPAD + k] = Wr[i];
        w1T[c * WPAD + k] = Wh1[i];
    }
    if (threadIdx.x < H) {
        bls[threadIdx.x] = bl[threadIdx.x];
        b1s[threadIdx.x] = bh1[threadIdx.x];
    }
    for (int i = threadIdx.x; i < H * 3; i += blockDim.x) W2s[i] = Wh2[i];
    if (threadIdx.x < 3) b2s[threadIdx.x] = bh2[threadIdx.x];
    __syncthreads();

    int lane  = threadIdx.x & 31;
    int w     = threadIdx.x >> 5;
    int gwarp = blockIdx.x * 8 + w;
    int sub = lane >> 3, q = lane & 7;
    const float4* h4 = (const float4*)g_hB;

    for (int p = gwarp; p < N_QUADS; p += L23_BLOCKS * 8) {
        int n0 = 4 * p;
        int off0 = g_offsets[n0];
        int off1 = g_offsets[n0 + 1];
        int off2 = g_offsets[n0 + 2];
        int off3 = g_offsets[n0 + 3];
        int off4 = g_offsets[n0 + 4];

        gather_mean(h4, off0, off1 - off0, sub, q, lane, ms4[0][w]);
        gather_mean(h4, off1, off2 - off1, sub, q, lane, ms4[1][w]);
        gather_mean(h4, off2, off3 - off2, sub, q, lane, ms4[2][w]);
        gather_mean(h4, off3, off4 - off3, sub, q, lane, ms4[3][w]);
#pragma unroll
        for (int j = 0; j < 4; j++) {
            ((float*)hs4[j][w])[lane] = __ldcg(&g_hB[(n0 + j) * H + lane]);
        }
        __syncwarp();

        const float4* wl4 = (const float4*)(wlT + lane * WPAD);
        const float4* wr4 = (const float4*)(wrT + lane * WPAD);
        float o0 = bls[lane], o1 = o0, o2 = o0, o3 = o0;
#pragma unroll
        for (int kk = 0; kk < 8; kk++) {
            float4 a4 = wl4[kk];
            float4 b4 = wr4[kk];
            float4 m0 = ms4[0][w][kk], v0 = hs4[0][w][kk];
            float4 m1 = ms4[1][w][kk], v1 = hs4[1][w][kk];
            float4 m2 = ms4[2][w][kk], v2 = hs4[2][w][kk];
            float4 m3 = ms4[3][w][kk], v3 = hs4[3][w][kk];
            o0 += m0.x * a4.x + m0.y * a4.y + m0.z * a4.z + m0.w * a4.w
                + v0.x * b4.x + v0.y * b4.y + v0.z * b4.z + v0.w * b4.w;
            o1 += m1.x * a4.x + m1.y * a4.y + m1.z * a4.z + m1.w * a4.w
                + v1.x * b4.x + v1.y * b4.y + v1.z * b4.z + v1.w * b4.w;
            o2 += m2.x * a4.x + m2.y * a4.y + m2.z * a4.z + m2.w * a4.w
                + v2.x * b4.x + v2.y * b4.y + v2.z * b4.z + v2.w * b4.w;
            o3 += m3.x * a4.x + m3.y * a4.y + m3.z * a4.z + m3.w * a4.w
                + v3.x * b4.x + v3.y * b4.y + v3.z * b4.z + v3.w * b4.w;
        }
        float h30 = fmaxf(o0, 0.f);
        float h31 = fmaxf(o1, 0.f);
        float h32 = fmaxf(o2, 0.f);
        float h33 = fmaxf(o3, 0.f);

        // head layer 1: 32 -> 32, relu (reuse hs buffers for h3 broadcast)
        __syncwarp();
        ((float*)hs4[0][w])[lane] = h30;
        ((float*)hs4[1][w])[lane] = h31;
        ((float*)hs4[2][w])[lane] = h32;
        ((float*)hs4[3][w])[lane] = h33;
        __syncwarp();
        const float4* w14 = (const float4*)(w1T + lane * WPAD);
        float t10 = b1s[lane], t11 = t10, t12 = t10, t13 = t10;
#pragma unroll
        for (int kk = 0; kk < 8; kk++) {
            float4 a4 = w14[kk];
            float4 v0 = hs4[0][w][kk];
            float4 v1 = hs4[1][w][kk];
            float4 v2 = hs4[2][w][kk];
            float4 v3 = hs4[3][w][kk];
            t10 += v0.x * a4.x + v0.y * a4.y + v0.z * a4.z + v0.w * a4.w;
            t11 += v1.x * a4.x + v1.y * a4.y + v1.z * a4.z + v1.w * a4.w;
            t12 += v2.x * a4.x + v2.y * a4.y + v2.z * a4.z + v2.w * a4.w;
            t13 += v3.x * a4.x + v3.y * a4.y + v3.z * a4.z + v3.w * a4.w;
        }
        t10 = fmaxf(t10, 0.f);
        t11 = fmaxf(t11, 0.f);
        t12 = fmaxf(t12, 0.f);
        t13 = fmaxf(t13, 0.f);

        // head layer 2: 32 -> 3, warp reductions for four nodes (two batches)
        float w0 = W2s[lane * 3 + 0], w1 = W2s[lane * 3 + 1], w2 = W2s[lane * 3 + 2];
        {
            float pA0 = t10 * w0, pA1 = t10 * w1, pA2 = t10 * w2;
            float pB0 = t11 * w0, pB1 = t11 * w1, pB2 = t11 * w2;
#pragma unroll
            for (int off = 16; off > 0; off >>= 1) {
                pA0 += __shfl_xor_sync(FULL, pA0, off);
                pA1 += __shfl_xor_sync(FULL, pA1, off);
                pA2 += __shfl_xor_sync(FULL, pA2, off);
                pB0 += __shfl_xor_sync(FULL, pB0, off);
                pB1 += __shfl_xor_sync(FULL, pB1, off);
                pB2 += __shfl_xor_sync(FULL, pB2, off);
            }
            if (lane == 0) {
                out[(n0 + 0) * 3 + 0] = pA0 + b2s[0];
                out[(n0 + 0) * 3 + 1] = pA1 + b2s[1];
                out[(n0 + 0) * 3 + 2] = pA2 + b2s[2];
                out[(n0 + 1) * 3 + 0] = pB0 + b2s[0];
                out[(n0 + 1) * 3 + 1] = pB1 + b2s[1];
                out[(n0 + 1) * 3 + 2] = pB2 + b2s[2];
            }
        }
        {
            float pA0 = t12 * w0, pA1 = t12 * w1, pA2 = t12 * w2;
            float pB0 = t13 * w0, pB1 = t13 * w1, pB2 = t13 * w2;
#pragma unroll
            for (int off = 16; off > 0; off >>= 1) {
                pA0 += __shfl_xor_sync(FULL, pA0, off);
                pA1 += __shfl_xor_sync(FULL, pA1, off);
                pA2 += __shfl_xor_sync(FULL, pA2, off);
                pB0 += __shfl_xor_sync(FULL, pB0, off);
                pB1 += __shfl_xor_sync(FULL, pB1, off);
                pB2 += __shfl_xor_sync(FULL, pB2, off);
            }
            if (lane == 0) {
                out[(n0 + 2) * 3 + 0] = pA0 + b2s[0];
                out[(n0 + 2) * 3 + 1] = pA1 + b2s[1];
                out[(n0 + 2) * 3 + 2] = pA2 + b2s[2];
                out[(n0 + 3) * 3 + 0] = pB0 + b2s[0];
                out[(n0 + 3) * 3 + 1] = pB1 + b2s[1];
                out[(n0 + 3) * 3 + 2] = pB2 + b2s[2];
            }
        }
        __syncwarp();
    }
}

// ---------------- launcher ---------------------------------------------------
extern "C" void kernel_launch(void* const* d_in, const int* in_sizes, int n_in,
                              void* d_out, int out_size) {
    const float* x   = (const float*)d_in[0];
    const int*   ei  = (const int*)d_in[1];    // int64 in reference -> int32 on device
    const int*   src = ei;
    const int*   dst = ei + N_EDGES;
    const float* Wl1 = (const float*)d_in[2];
    const float* bl1 = (const float*)d_in[3];
    const float* Wr1 = (const float*)d_in[4];
    const float* Wl2 = (const float*)d_in[5];
    const float* bl2 = (const float*)d_in[6];
    const float* Wr2 = (const float*)d_in[7];
    const float* Wl3 = (const float*)d_in[8];
    const float* bl3 = (const float*)d_in[9];
    const float* Wr3 = (const float*)d_in[10];
    const float* Wh1 = (const float*)d_in[11];
    const float* bh1 = (const float*)d_in[12];
    const float* Wh2 = (const float*)d_in[13];
    const float* bh2 = (const float*)d_in[14];
    float* out = (float*)d_out;

    k_hist<<<(N_EDGES / 4 + 255) / 256, 256>>>(dst);
    k_scan<<<NUM_SCAN_BLOCKS, 512>>>();
    k_fill<<<(N_EDGES / 4 + 255) / 256, 256>>>(src, dst);

    k_layer1<<<L1_BLOCKS, 256>>>(x, Wl1, bl1, Wr1);
    k_layer2<<<L23_BLOCKS, 256>>>(Wl2, bl2, Wr2);
    k_layer3_head<<<L23_BLOCKS, 256>>>(out, Wl3, bl3, Wr3, Wh1, bh1, Wh2, bh2);
}

// round 14
// speedup vs baseline: 1.2420x; 1.0445x over previous
#include <cuda_runtime.h>

#define N_NODES 100000
#define N_PAIRS (N_NODES / 2)
#define N_QUADS (N_NODES / 4)
#define N_EDGES 1600000
#define DIN 8
#define H 32
#define WPAD 36            // padded transposed-weight row stride (floats)
#define FULL 0xffffffffu

#define SCAN_ELEMS 2048
#define NUM_SCAN_BLOCKS ((N_NODES + SCAN_ELEMS - 1) / SCAN_ELEMS)   // 49
#define L1_BLOCKS  888     // layer1: 6 blocks/SM
#define L2_BLOCKS  888     // layer2: retry 6/SM now that epilogue is crossbar-light
#define L3_BLOCKS  592     // layer3+head: 4/SM (control)

// ---------------- scratch (device globals; no allocation allowed) ----------
__device__ int   g_counts[N_NODES];
__device__ int   g_offsets[N_NODES + 1];
__device__ int   g_rank[N_EDGES];
__device__ int   g_csr[N_EDGES];
__device__ float g_hA[N_NODES * H];
__device__ float g_hB[N_NODES * H];
__device__ int   g_blockAgg[NUM_SCAN_BLOCKS];
__device__ int   g_blockPrefix[NUM_SCAN_BLOCKS];
__device__ int   g_blockFlag[NUM_SCAN_BLOCKS];   // 0=none 1=agg 2=prefix
__device__ int   g_scanCounter;

// ---------------- hist (counts pre-zeroed by previous replay's k_fill) ------
__global__ void k_hist(const int* __restrict__ dst) {
    int i = blockIdx.x * blockDim.x + threadIdx.x;
    if (i < N_EDGES / 4) {
        int4 d = ((const int4*)dst)[i];
        int4 r;
        r.x = atomicAdd(&g_counts[d.x], 1);
        r.y = atomicAdd(&g_counts[d.y], 1);
        r.z = atomicAdd(&g_counts[d.z], 1);
        r.w = atomicAdd(&g_counts[d.w], 1);
        ((int4*)g_rank)[i] = r;
    }
}

// ---------------- single-pass decoupled-lookback exclusive scan --------------
__global__ void __launch_bounds__(512) k_scan() {
    __shared__ int s_warpSums[16];
    __shared__ int s_bid;
    __shared__ int s_exclBase;

    int t = threadIdx.x;
    if (t == 0) s_bid = atomicAdd(&g_scanCounter, 1);
    __syncthreads();
    int bid  = s_bid;
    int base = bid * SCAN_ELEMS;
    int idx  = base + t * 4;
    int lane = t & 31, wid = t >> 5;

    int4 v;
    if (idx + 3 < N_NODES) {
        v = ((const int4*)g_counts)[idx >> 2];
    } else {
        v.x = (idx + 0 < N_NODES) ? g_counts[idx + 0] : 0;
        v.y = (idx + 1 < N_NODES) ? g_counts[idx + 1] : 0;
        v.z = (idx + 2 < N_NODES) ? g_counts[idx + 2] : 0;
        v.w = (idx + 3 < N_NODES) ? g_counts[idx + 3] : 0;
    }
    int tsum = v.x + v.y + v.z + v.w;
    int tIncl = tsum;
#pragma unroll
    for (int off = 1; off < 32; off <<= 1) {
        int u = __shfl_up_sync(FULL, tIncl, off);
        if (lane >= off) tIncl += u;
    }
    if (lane == 31) s_warpSums[wid] = tIncl;
    __syncthreads();

    if (t == 0) {
        int run = 0;
#pragma unroll
        for (int i = 0; i < 16; i++) { int a = s_warpSums[i]; s_warpSums[i] = run; run += a; }
        if (bid == 0) {
            g_blockPrefix[0] = run;
            __threadfence();
            ((volatile int*)g_blockFlag)[0] = 2;
            s_exclBase = 0;
        } else {
            g_blockAgg[bid] = run;
            __threadfence();
            ((volatile int*)g_blockFlag)[bid] = 1;
            int running = 0;
            int j = bid - 1;
            while (true) {
                int f;
                while ((f = ((volatile int*)g_blockFlag)[j]) == 0) { }
                __threadfence();
                if (f == 2) { running += ((volatile int*)g_blockPrefix)[j]; break; }
                running += ((volatile int*)g_blockAgg)[j];
                j--;
            }
            g_blockPrefix[bid] = running + run;
            __threadfence();
            ((volatile int*)g_blockFlag)[bid] = 2;
            s_exclBase = running;
        }
    }
    __syncthreads();

    int e0 = s_exclBase + s_warpSums[wid] + (tIncl - tsum);
    int4 o;
    o.x = e0;
    o.y = e0 + v.x;
    o.z = o.y + v.y;
    o.w = o.z + v.z;
    if (idx + 3 < N_NODES) {
        ((int4*)g_offsets)[idx >> 2] = o;
    } else {
        if (idx + 0 < N_NODES) g_offsets[idx + 0] = o.x;
        if (idx + 1 < N_NODES) g_offsets[idx + 1] = o.y;
        if (idx + 2 < N_NODES) g_offsets[idx + 2] = o.z;
        if (idx + 3 < N_NODES) g_offsets[idx + 3] = o.w;
    }
}

// ---------------- fill (atomic-free) + re-zero state for next replay ---------
__global__ void k_fill(const int* __restrict__ src,
                       const int* __restrict__ dst) {
    int i = blockIdx.x * blockDim.x + threadIdx.x;
    if (i < N_EDGES / 4) {
        int4 d = ((const int4*)dst)[i];
        int4 s = ((const int4*)src)[i];
        int4 r = ((const int4*)g_rank)[i];
        g_csr[g_offsets[d.x] + r.x] = s.x;
        g_csr[g_offsets[d.y] + r.y] = s.y;
        g_csr[g_offsets[d.z] + r.z] = s.z;
        g_csr[g_offsets[d.w] + r.w] = s.w;
    }
    // counts are dead after k_scan; zero them for the NEXT graph replay
    if (i < N_NODES / 4) ((int4*)g_counts)[i] = make_int4(0, 0, 0, 0);
    if (i < NUM_SCAN_BLOCKS) g_blockFlag[i] = 0;
    if (i == 0) {
        g_scanCounter = 0;
        g_offsets[N_NODES] = N_EDGES;   // sentinel for cnt computation this replay
    }
}

// ---------------- layer1 gather helper (16 edges/iter, 8-dim rows) ----------
__device__ __forceinline__ void gather_mean8(const float4* __restrict__ x4,
                                             int base, int cnt,
                                             int sub, int q, int lane,
                                             float* msDst /* 8 floats */) {
    float4 acc = make_float4(0.f, 0.f, 0.f, 0.f);
    int s0 = (sub < cnt) ? g_csr[base + sub] : -1;
    for (int i = 0; i < cnt; i += 16) {
        int en = i + 16 + sub;
        int sn = (en < cnt) ? g_csr[base + en] : -1;
        if (s0 >= 0) {
            float4 v = __ldcg(&x4[s0 * 2 + q]);
            acc.x += v.x; acc.y += v.y; acc.z += v.z; acc.w += v.w;
        }
        s0 = sn;
    }
#pragma unroll
    for (int off = 16; off >= 2; off >>= 1) {
        acc.x += __shfl_down_sync(FULL, acc.x, off);
        acc.y += __shfl_down_sync(FULL, acc.y, off);
        acc.z += __shfl_down_sync(FULL, acc.z, off);
        acc.w += __shfl_down_sync(FULL, acc.w, off);
    }
    float inv = 1.f / fmaxf((float)cnt, 1.f);
    if (lane < 2) {
        ((float4*)msDst)[lane] = make_float4(acc.x * inv, acc.y * inv, acc.z * inv, acc.w * inv);
    }
}

// ---------------- layer 1: x[N,8] -> g_hA[N,32]  (PAIR-per-warp, R12 best) --
__global__ void __launch_bounds__(256, 6) k_layer1(const float* __restrict__ x,
                                                   const float* __restrict__ Wl,
                                                   const float* __restrict__ bl,
                                                   const float* __restrict__ Wr) {
    __shared__ float Wls[DIN * H], Wrs[DIN * H], bls[H];
    __shared__ float msA[8][8], msB[8][8];
    __shared__ float xsA[8][8], xsB[8][8];
    for (int i = threadIdx.x; i < DIN * H; i += blockDim.x) {
        Wls[i] = Wl[i];
        Wrs[i] = Wr[i];
    }
    if (threadIdx.x < H) bls[threadIdx.x] = bl[threadIdx.x];
    __syncthreads();

    int lane  = threadIdx.x & 31;
    int w     = threadIdx.x >> 5;
    int gwarp = blockIdx.x * 8 + w;
    int sub = lane >> 1, q = lane & 1;
    const float4* x4 = (const float4*)x;

    for (int p = gwarp; p < N_PAIRS; p += L1_BLOCKS * 8) {
        int nA = 2 * p, nB = 2 * p + 1;
        int baseA = g_offsets[nA];
        int baseB = g_offsets[nB];
        int endB  = g_offsets[nB + 1];
        int cntA = baseB - baseA;
        int cntB = endB - baseB;

        gather_mean8(x4, baseA, cntA, sub, q, lane, msA[w]);
        gather_mean8(x4, baseB, cntB, sub, q, lane, msB[w]);
        if (lane < 8) {
            xsA[w][lane] = __ldcg(&x[nA * DIN + lane]);
            xsB[w][lane] = __ldcg(&x[nB * DIN + lane]);
        }
        __syncwarp();

        float oA = bls[lane], oB = oA;
#pragma unroll
        for (int k = 0; k < DIN; k++) {
            float wl = Wls[k * H + lane];        // one weight load, two nodes
            float wr = Wrs[k * H + lane];
            oA += msA[w][k] * wl + xsA[w][k] * wr;
            oB += msB[w][k] * wl + xsB[w][k] * wr;
        }
        __stcg(&g_hA[nA * H + lane], fmaxf(oA, 0.f));
        __stcg(&g_hA[nB * H + lane], fmaxf(oB, 0.f));
        __syncwarp();
    }
}

// ---------------- gather + mean for one node (lean, 32-dim rows) -------------
__device__ __forceinline__ void gather_mean(const float4* __restrict__ h4,
                                            int base, int cnt,
                                            int sub, int q, int lane,
                                            float4* msDst) {
    float4 acc = make_float4(0.f, 0.f, 0.f, 0.f);
    int s0 = (sub < cnt) ? g_csr[base + sub] : -1;
    for (int i = 0; i < cnt; i += 4) {
        int en = i + 4 + sub;
        int sn = (en < cnt) ? g_csr[base + en] : -1;
        if (s0 >= 0) {
            float4 v = __ldcg(&h4[s0 * 8 + q]);
            acc.x += v.x; acc.y += v.y; acc.z += v.z; acc.w += v.w;
        }
        s0 = sn;
    }
#pragma unroll
    for (int off = 16; off >= 8; off >>= 1) {
        acc.x += __shfl_down_sync(FULL, acc.x, off);
        acc.y += __shfl_down_sync(FULL, acc.y, off);
        acc.z += __shfl_down_sync(FULL, acc.z, off);
        acc.w += __shfl_down_sync(FULL, acc.w, off);
    }
    float inv = 1.f / fmaxf((float)cnt, 1.f);
    if (lane < 8) {
        msDst[lane] = make_float4(acc.x * inv, acc.y * inv, acc.z * inv, acc.w * inv);
    }
}

// ---------------- layer 2: g_hA -> g_hB  (QUAD-per-warp, 888 blocks) ---------
__global__ void __launch_bounds__(256, 6) k_layer2(const float* __restrict__ Wl,
                                                   const float* __restrict__ bl,
                                                   const float* __restrict__ Wr) {
    __shared__ float wlT[H * WPAD], wrT[H * WPAD], bls[H];
    __shared__ float4 ms4[4][8][8], hs4[4][8][8];
    for (int i = threadIdx.x; i < H * H; i += blockDim.x) {
        int k = i >> 5, c = i & 31;
        wlT[c * WPAD + k] = Wl[i];
        wrT[c * WPAD + k] = Wr[i];
    }
    if (threadIdx.x < H) bls[threadIdx.x] = bl[threadIdx.x];
    __syncthreads();

    int lane  = threadIdx.x & 31;
    int w     = threadIdx.x >> 5;
    int gwarp = blockIdx.x * 8 + w;
    int sub = lane >> 3, q = lane & 7;
    const float4* h4 = (const float4*)g_hA;

    for (int p = gwarp; p < N_QUADS; p += L2_BLOCKS * 8) {
        int n0 = 4 * p;
        int off0 = g_offsets[n0];
        int off1 = g_offsets[n0 + 1];
        int off2 = g_offsets[n0 + 2];
        int off3 = g_offsets[n0 + 3];
        int off4 = g_offsets[n0 + 4];

        gather_mean(h4, off0, off1 - off0, sub, q, lane, ms4[0][w]);
        gather_mean(h4, off1, off2 - off1, sub, q, lane, ms4[1][w]);
        gather_mean(h4, off2, off3 - off2, sub, q, lane, ms4[2][w]);
        gather_mean(h4, off3, off4 - off3, sub, q, lane, ms4[3][w]);
#pragma unroll
        for (int j = 0; j < 4; j++) {
            ((float*)hs4[j][w])[lane] = __ldcg(&g_hA[(n0 + j) * H + lane]);
        }
        __syncwarp();

        const float4* wl4 = (const float4*)(wlT + lane * WPAD);
        const float4* wr4 = (const float4*)(wrT + lane * WPAD);
        float o0 = bls[lane], o1 = o0, o2 = o0, o3 = o0;
#pragma unroll
        for (int kk = 0; kk < 8; kk++) {
            float4 a4 = wl4[kk];                 // one weight load feeds FOUR nodes
            float4 b4 = wr4[kk];
            float4 m0 = ms4[0][w][kk], v0 = hs4[0][w][kk];
            float4 m1 = ms4[1][w][kk], v1 = hs4[1][w][kk];
            float4 m2 = ms4[2][w][kk], v2 = hs4[2][w][kk];
            float4 m3 = ms4[3][w][kk], v3 = hs4[3][w][kk];
            o0 += m0.x * a4.x + m0.y * a4.y + m0.z * a4.z + m0.w * a4.w
                + v0.x * b4.x + v0.y * b4.y + v0.z * b4.z + v0.w * b4.w;
            o1 += m1.x * a4.x + m1.y * a4.y + m1.z * a4.z + m1.w * a4.w
                + v1.x * b4.x + v1.y * b4.y + v1.z * b4.z + v1.w * b4.w;
            o2 += m2.x * a4.x + m2.y * a4.y + m2.z * a4.z + m2.w * a4.w
                + v2.x * b4.x + v2.y * b4.y + v2.z * b4.z + v2.w * b4.w;
            o3 += m3.x * a4.x + m3.y * a4.y + m3.z * a4.z + m3.w * a4.w
                + v3.x * b4.x + v3.y * b4.y + v3.z * b4.z + v3.w * b4.w;
        }
        __stcg(&g_hB[(n0 + 0) * H + lane], fmaxf(o0, 0.f));
        __stcg(&g_hB[(n0 + 1) * H + lane], fmaxf(o1, 0.f));
        __stcg(&g_hB[(n0 + 2) * H + lane], fmaxf(o2, 0.f));
        __stcg(&g_hB[(n0 + 3) * H + lane], fmaxf(o3, 0.f));
        __syncwarp();
    }
}

// ---------------- layer 3 + MLP head (QUAD-per-warp, 592 blocks) -------------
__global__ void __launch_bounds__(256) k_layer3_head(float* __restrict__ out,
                                                     const float* __restrict__ Wl,
                                                     const float* __restrict__ bl,
                                                     const float* __restrict__ Wr,
                                                     const float* __restrict__ Wh1,
                                                     const float* __restrict__ bh1,
                                                     const float* __restrict__ Wh2,
                                                     const float* __restrict__ bh2) {
    __shared__ float wlT[H * WPAD], wrT[H * WPAD], w1T[H * WPAD];
    __shared__ float bls[H], b1s[H], W2s[H * 3], b2s[3];
    __shared__ float4 ms4[4][8][8], hs4[4][8][8];
    for (int i = threadIdx.x; i < H * H; i += blockDim.x) {
        int k = i >> 5, c = i & 31;
        wlT[c * WPAD + k] = Wl[i];
        wrT[c * WPAD + k] = Wr[i];
        w1T[c * WPAD + k] = Wh1[i];
    }
    if (threadIdx.x < H) {
        bls[threadIdx.x] = bl[threadIdx.x];
        b1s[threadIdx.x] = bh1[threadIdx.x];
    }
    for (int i = threadIdx.x; i < H * 3; i += blockDim.x) W2s[i] = Wh2[i];
    if (threadIdx.x < 3) b2s[threadIdx.x] = bh2[threadIdx.x];
    __syncthreads();

    int lane  = threadIdx.x & 31;
    int w     = threadIdx.x >> 5;
    int gwarp = blockIdx.x * 8 + w;
    int sub = lane >> 3, q = lane & 7;
    const float4* h4 = (const float4*)g_hB;

    for (int p = gwarp; p < N_QUADS; p += L3_BLOCKS * 8) {
        int n0 = 4 * p;
        int off0 = g_offsets[n0];
        int off1 = g_offsets[n0 + 1];
        int off2 = g_offsets[n0 + 2];
        int off3 = g_offsets[n0 + 3];
        int off4 = g_offsets[n0 + 4];

        gather_mean(h4, off0, off1 - off0, sub, q, lane, ms4[0][w]);
        gather_mean(h4, off1, off2 - off1, sub, q, lane, ms4[1][w]);
        gather_mean(h4, off2, off3 - off2, sub, q, lane, ms4[2][w]);
        gather_mean(h4, off3, off4 - off3, sub, q, lane, ms4[3][w]);
#pragma unroll
        for (int j = 0; j < 4; j++) {
            ((float*)hs4[j][w])[lane] = __ldcg(&g_hB[(n0 + j) * H + lane]);
        }
        __syncwarp();

        const float4* wl4 = (const float4*)(wlT + lane * WPAD);
        const float4* wr4 = (const float4*)(wrT + lane * WPAD);
        float o0 = bls[lane], o1 = o0, o2 = o0, o3 = o0;
#pragma unroll
        for (int kk = 0; kk < 8; kk++) {
            float4 a4 = wl4[kk];
            float4 b4 = wr4[kk];
            float4 m0 = ms4[0][w][kk], v0 = hs4[0][w][kk];
            float4 m1 = ms4[1][w][kk], v1 = hs4[1][w][kk];
            float4 m2 = ms4[2][w][kk], v2 = hs4[2][w][kk];
            float4 m3 = ms4[3][w][kk], v3 = hs4[3][w][kk];
            o0 += m0.x * a4.x + m0.y * a4.y + m0.z * a4.z + m0.w * a4.w
                + v0.x * b4.x + v0.y * b4.y + v0.z * b4.z + v0.w * b4.w;
            o1 += m1.x * a4.x + m1.y * a4.y + m1.z * a4.z + m1.w * a4.w
                + v1.x * b4.x + v1.y * b4.y + v1.z * b4.z + v1.w * b4.w;
            o2 += m2.x * a4.x + m2.y * a4.y + m2.z * a4.z + m2.w * a4.w
                + v2.x * b4.x + v2.y * b4.y + v2.z * b4.z + v2.w * b4.w;
            o3 += m3.x * a4.x + m3.y * a4.y + m3.z * a4.z + m3.w * a4.w
                + v3.x * b4.x + v3.y * b4.y + v3.z * b4.z + v3.w * b4.w;
        }
        float h30 = fmaxf(o0, 0.f);
        float h31 = fmaxf(o1, 0.f);
        float h32 = fmaxf(o2, 0.f);
        float h33 = fmaxf(o3, 0.f);

        // head layer 1: 32 -> 32, relu (reuse hs buffers for h3 broadcast)
        __syncwarp();
        ((float*)hs4[0][w])[lane] = h30;
        ((float*)hs4[1][w])[lane] = h31;
        ((float*)hs4[2][w])[lane] = h32;
        ((float*)hs4[3][w])[lane] = h33;
        __syncwarp();
        const float4* w14 = (const float4*)(w1T + lane * WPAD);
        float t10 = b1s[lane], t11 = t10, t12 = t10, t13 = t10;
#pragma unroll
        for (int kk = 0; kk < 8; kk++) {
            float4 a4 = w14[kk];
            float4 v0 = hs4[0][w][kk];
            float4 v1 = hs4[1][w][kk];
            float4 v2 = hs4[2][w][kk];
            float4 v3 = hs4[3][w][kk];
            t10 += v0.x * a4.x + v0.y * a4.y + v0.z * a4.z + v0.w * a4.w;
            t11 += v1.x * a4.x + v1.y * a4.y + v1.z * a4.z + v1.w * a4.w;
            t12 += v2.x * a4.x + v2.y * a4.y + v2.z * a4.z + v2.w * a4.w;
            t13 += v3.x * a4.x + v3.y * a4.y + v3.z * a4.z + v3.w * a4.w;
        }
        t10 = fmaxf(t10, 0.f);
        t11 = fmaxf(t11, 0.f);
        t12 = fmaxf(t12, 0.f);
        t13 = fmaxf(t13, 0.f);

        // head layer 2: 32 -> 3, warp reductions for four nodes (two batches)
        float w0 = W2s[lane * 3 + 0], w1 = W2s[lane * 3 + 1], w2 = W2s[lane * 3 + 2];
        {
            float pA0 = t10 * w0, pA1 = t10 * w1, pA2 = t10 * w2;
            float pB0 = t11 * w0, pB1 = t11 * w1, pB2 = t11 * w2;
#pragma unroll
            for (int off = 16; off > 0; off >>= 1) {
                pA0 += __shfl_xor_sync(FULL, pA0, off);
                pA1 += __shfl_xor_sync(FULL, pA1, off);
                pA2 += __shfl_xor_sync(FULL, pA2, off);
                pB0 += __shfl_xor_sync(FULL, pB0, off);
                pB1 += __shfl_xor_sync(FULL, pB1, off);
                pB2 += __shfl_xor_sync(FULL, pB2, off);
            }
            if (lane == 0) {
                out[(n0 + 0) * 3 + 0] = pA0 + b2s[0];
                out[(n0 + 0) * 3 + 1] = pA1 + b2s[1];
                out[(n0 + 0) * 3 + 2] = pA2 + b2s[2];
                out[(n0 + 1) * 3 + 0] = pB0 + b2s[0];
                out[(n0 + 1) * 3 + 1] = pB1 + b2s[1];
                out[(n0 + 1) * 3 + 2] = pB2 + b2s[2];
            }
        }
        {
            float pA0 = t12 * w0, pA1 = t12 * w1, pA2 = t12 * w2;
            float pB0 = t13 * w0, pB1 = t13 * w1, pB2 = t13 * w2;
#pragma unroll
            for (int off = 16; off > 0; off >>= 1) {
                pA0 += __shfl_xor_sync(FULL, pA0, off);
                pA1 += __shfl_xor_sync(FULL, pA1, off);
                pA2 += __shfl_xor_sync(FULL, pA2, off);
                pB0 += __shfl_xor_sync(FULL, pB0, off);
                pB1 += __shfl_xor_sync(FULL, pB1, off);
                pB2 += __shfl_xor_sync(FULL, pB2, off);
            }
            if (lane == 0) {
                out[(n0 + 2) * 3 + 0] = pA0 + b2s[0];
                out[(n0 + 2) * 3 + 1] = pA1 + b2s[1];
                out[(n0 + 2) * 3 + 2] = pA2 + b2s[2];
                out[(n0 + 3) * 3 + 0] = pB0 + b2s[0];
                out[(n0 + 3) * 3 + 1] = pB1 + b2s[1];
                out[(n0 + 3) * 3 + 2] = pB2 + b2s[2];
            }
        }
        __syncwarp();
    }
}

// ---------------- launcher ---------------------------------------------------
extern "C" void kernel_launch(void* const* d_in, const int* in_sizes, int n_in,
                              void* d_out, int out_size) {
    const float* x   = (const float*)d_in[0];
    const int*   ei  = (const int*)d_in[1];    // int64 in reference -> int32 on device
    const int*   src = ei;
    const int*   dst = ei + N_EDGES;
    const float* Wl1 = (const float*)d_in[2];
    const float* bl1 = (const float*)d_in[3];
    const float* Wr1 = (const float*)d_in[4];
    const float* Wl2 = (const float*)d_in[5];
    const float* bl2 = (const float*)d_in[6];
    const float* Wr2 = (const float*)d_in[7];
    const float* Wl3 = (const float*)d_in[8];
    const float* bl3 = (const float*)d_in[9];
    const float* Wr3 = (const float*)d_in[10];
    const float* Wh1 = (const float*)d_in[11];
    const float* bh1 = (const float*)d_in[12];
    const float* Wh2 = (const float*)d_in[13];
    const float* bh2 = (const float*)d_in[14];
    float* out = (float*)d_out;

    k_hist<<<(N_EDGES / 4 + 255) / 256, 256>>>(dst);
    k_scan<<<NUM_SCAN_BLOCKS, 512>>>();
    k_fill<<<(N_EDGES / 4 + 255) / 256, 256>>>(src, dst);

    k_layer1<<<L1_BLOCKS, 256>>>(x, Wl1, bl1, Wr1);
    k_layer2<<<L2_BLOCKS, 256>>>(Wl2, bl2, Wr2);
    k_layer3_head<<<L3_BLOCKS, 256>>>(out, Wl3, bl3, Wr3, Wh1, bh1, Wh2, bh2);
}